// round 13
// baseline (speedup 1.0000x reference)
#include <cuda_runtime.h>
#include <cuda_bf16.h>
#include <math.h>
#include <stdint.h>

#define B_ 2
#define S_ 2048
#define E_ 512
#define H_ 8
#define DH_ 64
#define SCALE_ 0.125f  // 64^-0.5

#define BK 16          // fp32-equiv k per mainloop iter (k_mm)
#define SK 40          // k_mm smem row stride: 16 hi + 16 lo + 8 pad = 80B

typedef __nv_bfloat16 bf16;
typedef __nv_bfloat162 bf162;

// ---- scratch (device globals; allocation is forbidden) ----
__device__ bf16 g_qin_hi[4096 * 512], g_qin_lo[4096 * 512];
__device__ bf16 g_kin_hi[4096 * 512], g_kin_lo[4096 * 512];
__device__ bf16 g_vin_hi[4096 * 512], g_vin_lo[4096 * 512];
__device__ bf16 g_Wq_hi[512 * 512], g_Wq_lo[512 * 512];
__device__ bf16 g_Wk_hi[512 * 512], g_Wk_lo[512 * 512];
__device__ bf16 g_Wv_hi[512 * 512], g_Wv_lo[512 * 512];
__device__ bf16 g_Wo_hi[512 * 512], g_Wo_lo[512 * 512];
__device__ bf16 g_Q_hi[16 * 2048 * 64], g_Q_lo[16 * 2048 * 64];    // [bh][s][d]
__device__ bf16 g_K_hi[16 * 2048 * 64], g_K_lo[16 * 2048 * 64];    // [bh][s][d]
__device__ bf16 g_Vt_hi[16 * 64 * 2048], g_Vt_lo[16 * 64 * 2048];  // [bh][d][s]
__device__ bf16 g_C_hi[4096 * 512], g_C_lo[4096 * 512];            // ctx [m][e]
__device__ float g_tw[S_ * S_];
__device__ float g_pm[16 * 16 * 2048];   // [bh][ntile][row]
__device__ float g_pl[16 * 16 * 2048];

// ---------------------------------------------------------------------------
__global__ void tw_kernel(const float* __restrict__ ld) {
    int i = blockIdx.x * blockDim.x + threadIdx.x;
    float4 v = ((const float4*)ld)[i];
    ((float4*)g_tw)[i] =
        make_float4(__expf(-v.x), __expf(-v.y), __expf(-v.z), __expf(-v.w));
}

__device__ __forceinline__ void split4f(const float* __restrict__ src,
                                        bf16* __restrict__ hi,
                                        bf16* __restrict__ lo, int i) {
    float4 v = ((const float4*)src)[i];
    bf16 h0 = __float2bfloat16(v.x), h1 = __float2bfloat16(v.y);
    bf16 h2 = __float2bfloat16(v.z), h3 = __float2bfloat16(v.w);
    ((bf162*)hi)[2 * i]     = __halves2bfloat162(h0, h1);
    ((bf162*)hi)[2 * i + 1] = __halves2bfloat162(h2, h3);
    ((bf162*)lo)[2 * i] = __halves2bfloat162(
        __float2bfloat16(v.x - __bfloat162float(h0)),
        __float2bfloat16(v.y - __bfloat162float(h1)));
    ((bf162*)lo)[2 * i + 1] = __halves2bfloat162(
        __float2bfloat16(v.z - __bfloat162float(h2)),
        __float2bfloat16(v.w - __bfloat162float(h3)));
}

__global__ void split_in_kernel(const float* __restrict__ q,
                                const float* __restrict__ k,
                                const float* __restrict__ v) {
    int z = blockIdx.z;
    const float* src = (z == 0) ? q : (z == 1) ? k : v;
    bf16* hi = (z == 0) ? g_qin_hi : (z == 1) ? g_kin_hi : g_vin_hi;
    bf16* lo = (z == 0) ? g_qin_lo : (z == 1) ? g_kin_lo : g_vin_lo;
    split4f(src, hi, lo, blockIdx.x * 256 + threadIdx.x);
}

__global__ void split_w_kernel(const float* __restrict__ wq,
                               const float* __restrict__ wk,
                               const float* __restrict__ wv,
                               const float* __restrict__ wo) {
    int z = blockIdx.z;
    const float* src = (z == 0) ? wq : (z == 1) ? wk : (z == 2) ? wv : wo;
    bf16* hi = (z == 0) ? g_Wq_hi : (z == 1) ? g_Wk_hi : (z == 2) ? g_Wv_hi : g_Wo_hi;
    bf16* lo = (z == 0) ? g_Wq_lo : (z == 1) ? g_Wk_lo : (z == 2) ? g_Wv_lo : g_Wo_lo;
    split4f(src, hi, lo, blockIdx.x * 256 + threadIdx.x);
}

// ---------------------------------------------------------------------------
__device__ __forceinline__ void ldsm4(uint32_t addr, uint32_t& r0, uint32_t& r1,
                                      uint32_t& r2, uint32_t& r3) {
    asm volatile("ldmatrix.sync.aligned.m8n8.x4.shared.b16 {%0,%1,%2,%3}, [%4];"
                 : "=r"(r0), "=r"(r1), "=r"(r2), "=r"(r3) : "r"(addr));
}

__device__ __forceinline__ void mma16816(float* c, const uint32_t* a, const uint32_t* b) {
    asm volatile(
        "mma.sync.aligned.m16n8k16.row.col.f32.bf16.bf16.f32 "
        "{%0,%1,%2,%3}, {%4,%5,%6,%7}, {%8,%9}, {%0,%1,%2,%3};\n"
        : "+f"(c[0]), "+f"(c[1]), "+f"(c[2]), "+f"(c[3])
        : "r"(a[0]), "r"(a[1]), "r"(a[2]), "r"(a[3]), "r"(b[0]), "r"(b[1]));
}

__device__ __forceinline__ void cpa16(uint32_t dst, const void* src) {
    asm volatile("cp.async.cg.shared.global [%0], [%1], 16;" :: "r"(dst), "l"(src));
}
__device__ __forceinline__ void cp_commit() { asm volatile("cp.async.commit_group;"); }
template <int N>
__device__ __forceinline__ void cp_wait() { asm volatile("cp.async.wait_group %0;" :: "n"(N)); }

// [ROWS x 16] hi+lo tile loader, row layout [hi16|lo16|pad8], stride SK
template <int ROWS>
__device__ __forceinline__ void stage_load(const bf16* __restrict__ hi,
                                           const bf16* __restrict__ lo,
                                           int lda, int k0, uint32_t sdst, int tid) {
    #pragma unroll
    for (int i = 0; i < ROWS * 4 / 256; i++) {
        int idx = tid + i * 256;
        int r = idx >> 2, c = idx & 3;
        const bf16* src = ((c < 2) ? hi : lo) + (size_t)r * lda + k0 + (c & 1) * 8;
        uint32_t dst = sdst + (r * SK + ((c < 2) ? 0 : 16) + (c & 1) * 8) * 2;
        cpa16(dst, src);
    }
}

// ---------------------------------------------------------------------------
// 128x128 GEMM, 3xBF16, 4-stage cp.async pipeline, 1 sync/iter.
// Fragment reuse: aH/aL/bH/bL loaded once per k-step (12 LDSM, 48 MMA).
// MODE 5: fused QKV projections (z = 0/1/2 -> Q/K/V)
// MODE 2: scores (raw s + per-tile row stats)
// MODE 1: output projection -> fp32 out
// ---------------------------------------------------------------------------
template <int MODE>
__global__ __launch_bounds__(256, 2) void k_mm(
    const float* __restrict__ b0, const float* __restrict__ b1,
    const float* __restrict__ b2, float* __restrict__ out,
    const int* __restrict__ mask, const float* __restrict__ tbias) {
    constexpr int NST = 4;
    constexpr int STB = 256 * SK * 2;        // bytes per stage (A 128 rows + B 128 rows)
    constexpr int K = (MODE == 2) ? 64 : 512;
    constexpr int niter = K / BK;

    extern __shared__ char smraw[];
    float* red_s  = (float*)(smraw + NST * STB);        // [4][128]
    float* rowm_s = red_s + 4 * 128;

    const int tid = threadIdx.x, wid = tid >> 5, lane = tid & 31;
    const int wm = wid & 1, wn = wid >> 1;   // WARPS_M=2, WARPS_N=4; WM=64, WN=32
    const int bz = blockIdx.z;
    const int m0 = blockIdx.y * 128, n0 = blockIdx.x * 128;

    const bf16 *Ahi, *Alo, *Bhi, *Blo;
    const float* bias = b0;
    if (MODE == 5) {
        if (bz == 0)      { Ahi = g_qin_hi; Alo = g_qin_lo; Bhi = g_Wq_hi; Blo = g_Wq_lo; bias = b0; }
        else if (bz == 1) { Ahi = g_kin_hi; Alo = g_kin_lo; Bhi = g_Wk_hi; Blo = g_Wk_lo; bias = b1; }
        else              { Ahi = g_vin_hi; Alo = g_vin_lo; Bhi = g_Wv_hi; Blo = g_Wv_lo; bias = b2; }
    } else if (MODE == 1) {
        Ahi = g_C_hi; Alo = g_C_lo; Bhi = g_Wo_hi; Blo = g_Wo_lo;
    } else {  // MODE 2
        size_t o = (size_t)bz * S_ * DH_;
        Ahi = g_Q_hi + o; Alo = g_Q_lo + o; Bhi = g_K_hi + o; Blo = g_K_lo + o;
    }
    const bf16* Ahp = Ahi + (size_t)m0 * K;
    const bf16* Alp = Alo + (size_t)m0 * K;
    const bf16* Bhp = Bhi + (size_t)n0 * K;
    const bf16* Blp = Blo + (size_t)n0 * K;

    float acc[4][4][4];
    #pragma unroll
    for (int i = 0; i < 4; i++)
        #pragma unroll
        for (int j = 0; j < 4; j++)
            #pragma unroll
            for (int q = 0; q < 4; q++) acc[i][j][q] = 0.f;

    const uint32_t sbase = (uint32_t)__cvta_generic_to_shared(smraw);
    const int t8 = lane >> 3, r8 = lane & 7;
    const int frow = r8 + 8 * (t8 & 1);
    const int fcol = 8 * (t8 >> 1);

    // prologue: stages 0..NST-2
    #pragma unroll
    for (int s = 0; s < NST - 1; s++) {
        stage_load<128>(Ahp, Alp, K, s * BK, sbase + s * STB, tid);
        stage_load<128>(Bhp, Blp, K, s * BK, sbase + s * STB + 128 * SK * 2, tid);
        cp_commit();
    }

    for (int it = 0; it < niter; it++) {
        cp_wait<NST - 2>();
        __syncthreads();
        int pf = it + NST - 1;
        if (pf < niter) {
            uint32_t sd = sbase + (pf % NST) * STB;
            stage_load<128>(Ahp, Alp, K, pf * BK, sd, tid);
            stage_load<128>(Bhp, Blp, K, pf * BK, sd + 128 * SK * 2, tid);
        }
        cp_commit();

        const uint32_t sA = sbase + (it % NST) * STB;
        const uint32_t sB = sA + 128 * SK * 2;

        // load A-hi, B-hi, B-lo once
        uint32_t aH[4][4], bH[4][2], bL[4][2];
        #pragma unroll
        for (int mf = 0; mf < 4; mf++) {
            uint32_t addr = sA + ((wm * 64 + mf * 16 + frow) * SK + fcol) * 2;
            ldsm4(addr, aH[mf][0], aH[mf][1], aH[mf][2], aH[mf][3]);
        }
        #pragma unroll
        for (int nf2 = 0; nf2 < 2; nf2++) {
            uint32_t r0, r1, r2, r3;
            uint32_t addr = sB + ((wn * 32 + nf2 * 16 + frow) * SK + fcol) * 2;
            ldsm4(addr, r0, r1, r2, r3);
            bH[2 * nf2][0] = r0;      bH[2 * nf2][1] = r2;
            bH[2 * nf2 + 1][0] = r1;  bH[2 * nf2 + 1][1] = r3;
            addr = sB + ((wn * 32 + nf2 * 16 + frow) * SK + 16 + fcol) * 2;
            ldsm4(addr, r0, r1, r2, r3);
            bL[2 * nf2][0] = r0;      bL[2 * nf2][1] = r2;
            bL[2 * nf2 + 1][0] = r1;  bL[2 * nf2 + 1][1] = r3;
        }
        // pass 1: hi*hi
        #pragma unroll
        for (int mf = 0; mf < 4; mf++)
            #pragma unroll
            for (int nf = 0; nf < 4; nf++)
                mma16816(acc[mf][nf], aH[mf], bH[nf]);
        // pass 2: hi*lo
        #pragma unroll
        for (int mf = 0; mf < 4; mf++)
            #pragma unroll
            for (int nf = 0; nf < 4; nf++)
                mma16816(acc[mf][nf], aH[mf], bL[nf]);
        // load A-lo (aH now dead), pass 3: lo*hi
        uint32_t aL[4][4];
        #pragma unroll
        for (int mf = 0; mf < 4; mf++) {
            uint32_t addr = sA + ((wm * 64 + mf * 16 + frow) * SK + 16 + fcol) * 2;
            ldsm4(addr, aL[mf][0], aL[mf][1], aL[mf][2], aL[mf][3]);
        }
        #pragma unroll
        for (int mf = 0; mf < 4; mf++)
            #pragma unroll
            for (int nf = 0; nf < 4; nf++)
                mma16816(acc[mf][nf], aL[mf], bH[nf]);
    }

    const int lrow = lane >> 2, lcol = (lane & 3) * 2;
    #pragma unroll
    for (int mf = 0; mf < 4; mf++) {
        #pragma unroll
        for (int nf = 0; nf < 4; nf++) {
            #pragma unroll
            for (int hh = 0; hh < 2; hh++) {
                int m = m0 + wm * 64 + mf * 16 + lrow + hh * 8;
                int n = n0 + wn * 32 + nf * 8 + lcol;
                float v0 = acc[mf][nf][2 * hh];
                float v1 = acc[mf][nf][2 * hh + 1];
                if (MODE == 5) {
                    int b = m >> 11, s = m & 2047;
                    int h = n >> 6, d = n & 63;
                    float x0 = v0 + bias[n], x1 = v1 + bias[n + 1];
                    bf16 h0 = __float2bfloat16(x0), h1 = __float2bfloat16(x1);
                    bf16 l0 = __float2bfloat16(x0 - __bfloat162float(h0));
                    bf16 l1 = __float2bfloat16(x1 - __bfloat162float(h1));
                    if (bz < 2) {
                        bf16* oh = (bz == 0) ? g_Q_hi : g_K_hi;
                        bf16* ol = (bz == 0) ? g_Q_lo : g_K_lo;
                        size_t o = (((size_t)(b * H_ + h) * S_ + s) << 6) + d;
                        *(bf162*)&oh[o] = __halves2bfloat162(h0, h1);
                        *(bf162*)&ol[o] = __halves2bfloat162(l0, l1);
                    } else {
                        size_t base = (size_t)(b * H_ + h) * DH_;
                        g_Vt_hi[(base + d) * S_ + s] = h0;
                        g_Vt_hi[(base + d + 1) * S_ + s] = h1;
                        g_Vt_lo[(base + d) * S_ + s] = l0;
                        g_Vt_lo[(base + d + 1) * S_ + s] = l1;
                    }
                } else if (MODE == 1) {
                    *(float2*)&out[(size_t)m * 512 + n] =
                        make_float2(v0 + bias[n], v1 + bias[n + 1]);
                } else {  // MODE 2
                    int h = bz & 7;
                    float tb = tbias[h];
                    size_t mn = (size_t)m * S_ + n;
                    float2 tw = *(const float2*)&g_tw[mn];
                    int2 mk = *(const int2*)&mask[mn];
                    float s0 = v0 * SCALE_ + tb * tw.x;
                    float s1 = v1 * SCALE_ + tb * tw.y;
                    if (mk.x == 0) s0 = -1e9f;
                    if (mk.y == 0) s1 = -1e9f;
                    *(float2*)&out[(size_t)bz * S_ * S_ + mn] = make_float2(s0, s1);
                    acc[mf][nf][2 * hh] = s0;
                    acc[mf][nf][2 * hh + 1] = s1;
                }
            }
        }
    }

    if (MODE == 2) {
        #pragma unroll
        for (int mf = 0; mf < 4; mf++) {
            #pragma unroll
            for (int hh = 0; hh < 2; hh++) {
                float mx = -INFINITY;
                #pragma unroll
                for (int nf = 0; nf < 4; nf++)
                    mx = fmaxf(mx, fmaxf(acc[mf][nf][2 * hh], acc[mf][nf][2 * hh + 1]));
                mx = fmaxf(mx, __shfl_xor_sync(0xffffffffu, mx, 1));
                mx = fmaxf(mx, __shfl_xor_sync(0xffffffffu, mx, 2));
                if ((lane & 3) == 0)
                    red_s[wn * 128 + wm * 64 + mf * 16 + lrow + hh * 8] = mx;
            }
        }
        __syncthreads();
        if (tid < 128) {
            float mx = red_s[tid];
            #pragma unroll
            for (int w = 1; w < 4; w++) mx = fmaxf(mx, red_s[w * 128 + tid]);
            rowm_s[tid] = mx;
        }
        __syncthreads();
        #pragma unroll
        for (int mf = 0; mf < 4; mf++) {
            #pragma unroll
            for (int hh = 0; hh < 2; hh++) {
                int row = wm * 64 + mf * 16 + lrow + hh * 8;
                float rm = rowm_s[row];
                float sm = 0.f;
                #pragma unroll
                for (int nf = 0; nf < 4; nf++)
                    sm += __expf(acc[mf][nf][2 * hh] - rm) +
                          __expf(acc[mf][nf][2 * hh + 1] - rm);
                sm += __shfl_xor_sync(0xffffffffu, sm, 1);
                sm += __shfl_xor_sync(0xffffffffu, sm, 2);
                if ((lane & 3) == 0) red_s[wn * 128 + row] = sm;
            }
        }
        __syncthreads();
        if (tid < 128) {
            float l = red_s[tid];
            #pragma unroll
            for (int w = 1; w < 4; w++) l += red_s[w * 128 + tid];
            size_t o = ((size_t)bz * 16 + blockIdx.x) * S_ + m0 + tid;
            g_pm[o] = rowm_s[tid];
            g_pl[o] = l;
        }
    }
}

// ---------------------------------------------------------------------------
// ctx: raw s -> softmax finalize -> fp32 P -> P.V (3xBF16 mma.sync).
// Convert-ahead single-barrier pipeline:
//   barrier; prefetch(it+2); convert(it+1) -> sP[(it+1)&1]; MMA(it) on sP[it&1]
// smem layout (102400 B total, unchanged occupancy):
//   [0, 36864)        sS: 2 stages x 128 rows x 36 floats
//   [36864, 64512)    sV: 3 stages x 64 rows x 72 bf16
//   [64512, 101376)   sP: 2 buffers x 128 rows x 72 bf16
//   [101376, 102400)  sm_m[128], sm_li[128]
// ---------------------------------------------------------------------------
__global__ __launch_bounds__(256, 2) void ctx_kernel(float* __restrict__ P) {
    extern __shared__ char smraw[];
    float* sm_m  = (float*)(smraw + 101376);
    float* sm_li = (float*)(smraw + 101888);

    const int tid = threadIdx.x, wid = tid >> 5, lane = tid & 31;
    const int wm = wid & 3, wn = wid >> 2;
    const int bz = blockIdx.z;
    const int b = bz >> 3, h = bz & 7;
    const int m0 = blockIdx.y * 128;

    float* Pbh = P + (size_t)bz * S_ * S_;
    const bf16* Vh0 = g_Vt_hi + (size_t)bz * DH_ * S_;
    const bf16* Vl0 = g_Vt_lo + (size_t)bz * DH_ * S_;

    const uint32_t sbase = (uint32_t)__cvta_generic_to_shared(smraw);
    const int t8 = lane >> 3, r8 = lane & 7;
    const int frow = r8 + 8 * (t8 & 1), fcol = 8 * (t8 >> 1);
    const int lrow = lane >> 2, lcol = (lane & 3) * 2;

    auto loadS = [&](int it, int slot) {
        uint32_t dstb = sbase + slot * 18432;
        #pragma unroll
        for (int i = 0; i < 4; i++) {
            int idx = tid + i * 256;
            int r = idx >> 3, c = (idx & 7) * 4;
            cpa16(dstb + (r * 36 + c) * 4, Pbh + (size_t)(m0 + r) * S_ + it * 32 + c);
        }
    };
    auto loadV = [&](int it, int slot) {
        uint32_t dstb = sbase + 36864 + slot * 9216;
        #pragma unroll
        for (int i = 0; i < 2; i++) {
            int idx = tid + i * 256;
            int r = idx >> 3, c = idx & 7;
            const bf16* src = ((c < 4) ? Vh0 : Vl0) + (size_t)r * S_ + it * 32 + (c & 3) * 8;
            cpa16(dstb + (r * 72 + ((c < 4) ? 0 : 32) + (c & 3) * 8) * 2, src);
        }
    };

    const int cr = tid >> 1, cb = (tid & 1) * 16;
    // convert(j): finalize p = exp(s-m)*linv from sS[j&1], write fp32 P, split to sP[j&1]
    auto convert = [&](int j) {
        const float* ss = (const float*)(smraw + (j & 1) * 18432) + cr * 36 + cb;
        float mrow = sm_m[cr], li = sm_li[cr];
        float p[16];
        #pragma unroll
        for (int i = 0; i < 16; i += 4) {
            float4 a = *(const float4*)(ss + i);
            p[i]     = __expf(a.x - mrow) * li;
            p[i + 1] = __expf(a.y - mrow) * li;
            p[i + 2] = __expf(a.z - mrow) * li;
            p[i + 3] = __expf(a.w - mrow) * li;
        }
        float* gdst = Pbh + (size_t)(m0 + cr) * S_ + j * 32 + cb;
        #pragma unroll
        for (int i = 0; i < 16; i += 4)
            *(float4*)(gdst + i) = make_float4(p[i], p[i + 1], p[i + 2], p[i + 3]);
        bf16* sp = (bf16*)(smraw + 64512 + (j & 1) * 18432) + cr * 72;
        #pragma unroll
        for (int i = 0; i < 16; i += 8) {
            uint4 hv, lv;
            #pragma unroll
            for (int jj = 0; jj < 8; jj += 2) {
                bf16 a0 = __float2bfloat16(p[i + jj]);
                bf16 a1 = __float2bfloat16(p[i + jj + 1]);
                ((bf162*)&hv)[jj >> 1] = __halves2bfloat162(a0, a1);
                ((bf162*)&lv)[jj >> 1] = __halves2bfloat162(
                    __float2bfloat16(p[i + jj] - __bfloat162float(a0)),
                    __float2bfloat16(p[i + jj + 1] - __bfloat162float(a1)));
            }
            *(uint4*)(sp + cb + i) = hv;
            *(uint4*)(sp + 32 + cb + i) = lv;
        }
    };

    // prologue
    loadS(0, 0); loadV(0, 0); cp_commit();
    loadS(1, 1); loadV(1, 1); cp_commit();

    // stats combine — overlaps the prologue cp.async
    if (tid < 128) {
        int r = m0 + tid;
        float mt[16], mx = -INFINITY;
        #pragma unroll
        for (int t = 0; t < 16; t++) {
            mt[t] = g_pm[((size_t)bz * 16 + t) * S_ + r];
            mx = fmaxf(mx, mt[t]);
        }
        float l = 0.f;
        #pragma unroll
        for (int t = 0; t < 16; t++)
            l += g_pl[((size_t)bz * 16 + t) * S_ + r] * __expf(mt[t] - mx);
        sm_m[tid]  = mx;
        sm_li[tid] = 1.0f / l;
    }

    float acc[2][4][4];
    #pragma unroll
    for (int i = 0; i < 2; i++)
        #pragma unroll
        for (int j = 0; j < 4; j++)
            #pragma unroll
            for (int q = 0; q < 4; q++) acc[i][j][q] = 0.f;

    cp_wait<1>();
    __syncthreads();       // stage 0 loaded; sm_m/sm_li visible
    convert(0);

    for (int it = 0; it < 64; it++) {
        cp_wait<0>();      // all committed loads (incl. it+1) complete
        __syncthreads();   // convert(it)'s sP writes + loads visible to all
        if (it + 2 < 64) { loadS(it + 2, (it + 2) & 1); loadV(it + 2, (it + 2) % 3); cp_commit(); }
        if (it + 1 < 64) convert(it + 1);

        const uint32_t uP  = sbase + 64512 + (it & 1) * 18432;
        const uint32_t sVt = sbase + 36864 + (it % 3) * 9216;
        #pragma unroll
        for (int ks = 0; ks < 32; ks += 16) {
            uint32_t pH[2][4], pL[2][4], vH[4][2], vL[4][2];
            #pragma unroll
            for (int mf = 0; mf < 2; mf++) {
                uint32_t base = uP + ((wm * 32 + mf * 16 + frow) * 72 + ks + fcol) * 2;
                ldsm4(base, pH[mf][0], pH[mf][1], pH[mf][2], pH[mf][3]);
                ldsm4(base + 64, pL[mf][0], pL[mf][1], pL[mf][2], pL[mf][3]);
            }
            #pragma unroll
            for (int nf2 = 0; nf2 < 2; nf2++) {
                uint32_t r0, r1, r2, r3;
                uint32_t base = sVt + ((wn * 32 + nf2 * 16 + frow) * 72 + ks + fcol) * 2;
                ldsm4(base, r0, r1, r2, r3);
                vH[2 * nf2][0] = r0;      vH[2 * nf2][1] = r2;
                vH[2 * nf2 + 1][0] = r1;  vH[2 * nf2 + 1][1] = r3;
                ldsm4(base + 64, r0, r1, r2, r3);
                vL[2 * nf2][0] = r0;      vL[2 * nf2][1] = r2;
                vL[2 * nf2 + 1][0] = r1;  vL[2 * nf2 + 1][1] = r3;
            }
            #pragma unroll
            for (int mf = 0; mf < 2; mf++)
                #pragma unroll
                for (int nf = 0; nf < 4; nf++)
                    mma16816(acc[mf][nf], pH[mf], vH[nf]);
            #pragma unroll
            for (int mf = 0; mf < 2; mf++)
                #pragma unroll
                for (int nf = 0; nf < 4; nf++)
                    mma16816(acc[mf][nf], pH[mf], vL[nf]);
            #pragma unroll
            for (int mf = 0; mf < 2; mf++)
                #pragma unroll
                for (int nf = 0; nf < 4; nf++)
                    mma16816(acc[mf][nf], pL[mf], vH[nf]);
        }
    }

    #pragma unroll
    for (int mf = 0; mf < 2; mf++) {
        #pragma unroll
        for (int nf = 0; nf < 4; nf++) {
            #pragma unroll
            for (int hh = 0; hh < 2; hh++) {
                int m = m0 + wm * 32 + mf * 16 + lrow + hh * 8;
                int d = wn * 32 + nf * 8 + lcol;
                size_t o = ((size_t)b * S_ + m) * E_ + h * DH_ + d;
                float v0 = acc[mf][nf][2 * hh], v1 = acc[mf][nf][2 * hh + 1];
                bf16 h0 = __float2bfloat16(v0), h1 = __float2bfloat16(v1);
                *(bf162*)&g_C_hi[o] = __halves2bfloat162(h0, h1);
                *(bf162*)&g_C_lo[o] = __halves2bfloat162(
                    __float2bfloat16(v0 - __bfloat162float(h0)),
                    __float2bfloat16(v1 - __bfloat162float(h1)));
            }
        }
    }
}

// ---------------------------------------------------------------------------
extern "C" void kernel_launch(void* const* d_in, const int* in_sizes, int n_in,
                              void* d_out, int out_size) {
    const float* query = (const float*)d_in[0];
    const float* key   = (const float*)d_in[1];
    const float* value = (const float*)d_in[2];
    const int*   tmask = (const int*)d_in[3];
    const float* ldist = (const float*)d_in[4];
    const float* bq = (const float*)d_in[6];
    const float* bk = (const float*)d_in[8];
    const float* bv = (const float*)d_in[10];
    const float* bo = (const float*)d_in[12];
    const float* tbias = (const float*)d_in[13];

    float* out_attn  = (float*)d_out;
    float* out_probs = (float*)d_out + (size_t)B_ * S_ * E_;

    static int configured = 0;
    if (!configured) {
        cudaFuncSetAttribute(k_mm<5>, cudaFuncAttributeMaxDynamicSharedMemorySize, 84480);
        cudaFuncSetAttribute(k_mm<2>, cudaFuncAttributeMaxDynamicSharedMemorySize, 84480);
        cudaFuncSetAttribute(k_mm<1>, cudaFuncAttributeMaxDynamicSharedMemorySize, 84480);
        cudaFuncSetAttribute(ctx_kernel, cudaFuncAttributeMaxDynamicSharedMemorySize, 102400);
        configured = 1;
    }

    // preprocessing
    tw_kernel<<<4096, 256>>>(ldist);
    dim3 gi(2048, 1, 3);
    split_in_kernel<<<gi, 256>>>(query, key, value);
    dim3 gw(256, 1, 4);
    split_w_kernel<<<gw, 256>>>((const float*)d_in[5], (const float*)d_in[7],
                                (const float*)d_in[9], (const float*)d_in[11]);

    // fused QKV projections
    dim3 gqkv(4, 32, 3);
    k_mm<5><<<gqkv, 256, 84480>>>(bq, bk, bv, nullptr, nullptr, nullptr);

    // scores (raw s + per-tile stats)
    dim3 gs(16, 16, 16);
    k_mm<2><<<gs, 256, 84480>>>(nullptr, nullptr, nullptr, out_probs, tmask, tbias);

    // ctx: inline stats combine + softmax finalize + P.V (convert-ahead pipeline)
    dim3 gc(1, 16, 16);
    ctx_kernel<<<gc, 256, 102400>>>(out_probs);

    // output projection
    dim3 gp(4, 32, 1);
    k_mm<1><<<gp, 256, 84480>>>(bo, nullptr, nullptr, out_attn, nullptr, nullptr);
}

// round 14
// speedup vs baseline: 1.0443x; 1.0443x over previous
#include <cuda_runtime.h>
#include <cuda_bf16.h>
#include <math.h>
#include <stdint.h>

#define B_ 2
#define S_ 2048
#define E_ 512
#define H_ 8
#define DH_ 64
#define SCALE_ 0.125f  // 64^-0.5

#define BK 16          // fp32-equiv k per mainloop iter (k_mm)
#define SK 40          // k_mm smem row stride: 16 hi + 16 lo + 8 pad = 80B

typedef __nv_bfloat16 bf16;
typedef __nv_bfloat162 bf162;

// ---- scratch (device globals; allocation is forbidden) ----
__device__ bf16 g_qin_hi[4096 * 512], g_qin_lo[4096 * 512];
__device__ bf16 g_kin_hi[4096 * 512], g_kin_lo[4096 * 512];
__device__ bf16 g_vin_hi[4096 * 512], g_vin_lo[4096 * 512];
__device__ bf16 g_Wq_hi[512 * 512], g_Wq_lo[512 * 512];
__device__ bf16 g_Wk_hi[512 * 512], g_Wk_lo[512 * 512];
__device__ bf16 g_Wv_hi[512 * 512], g_Wv_lo[512 * 512];
__device__ bf16 g_Wo_hi[512 * 512], g_Wo_lo[512 * 512];
__device__ bf16 g_Q_hi[16 * 2048 * 64], g_Q_lo[16 * 2048 * 64];    // [bh][s][d]
__device__ bf16 g_K_hi[16 * 2048 * 64], g_K_lo[16 * 2048 * 64];    // [bh][s][d]
__device__ bf16 g_Vt_hi[16 * 64 * 2048], g_Vt_lo[16 * 64 * 2048];  // [bh][d][s]
__device__ bf16 g_C_hi[4096 * 512], g_C_lo[4096 * 512];            // ctx [m][e]
__device__ float g_ctw[S_ * S_];         // mask ? exp(-ld) : -1.0 sentinel
__device__ float g_pm[16 * 16 * 2048];   // [bh][ntile][row]
__device__ float g_pl[16 * 16 * 2048];

// ---------------------------------------------------------------------------
__device__ __forceinline__ void split4f(const float* __restrict__ src,
                                        bf16* __restrict__ hi,
                                        bf16* __restrict__ lo, int i) {
    float4 v = ((const float4*)src)[i];
    bf16 h0 = __float2bfloat16(v.x), h1 = __float2bfloat16(v.y);
    bf16 h2 = __float2bfloat16(v.z), h3 = __float2bfloat16(v.w);
    ((bf162*)hi)[2 * i]     = __halves2bfloat162(h0, h1);
    ((bf162*)hi)[2 * i + 1] = __halves2bfloat162(h2, h3);
    ((bf162*)lo)[2 * i] = __halves2bfloat162(
        __float2bfloat16(v.x - __bfloat162float(h0)),
        __float2bfloat16(v.y - __bfloat162float(h1)));
    ((bf162*)lo)[2 * i + 1] = __halves2bfloat162(
        __float2bfloat16(v.z - __bfloat162float(h2)),
        __float2bfloat16(v.w - __bfloat162float(h3)));
}

// one z-batched preprocessing launch:
//   z 0..2 : input splits (524288 float4)   z 3..6 : weight splits (65536 float4)
//   z 7    : ctw = mask ? exp(-ld) : -1     (1048576 float4)
__global__ void prep_kernel(const float* __restrict__ q, const float* __restrict__ k,
                            const float* __restrict__ v, const float* __restrict__ wq,
                            const float* __restrict__ wk, const float* __restrict__ wv,
                            const float* __restrict__ wo, const float* __restrict__ ld,
                            const int* __restrict__ mask) {
    int z = blockIdx.z;
    int i = blockIdx.x * 256 + threadIdx.x;
    if (z < 3) {
        if (i >= 4096 * 512 / 4) return;
        const float* src = (z == 0) ? q : (z == 1) ? k : v;
        bf16* hi = (z == 0) ? g_qin_hi : (z == 1) ? g_kin_hi : g_vin_hi;
        bf16* lo = (z == 0) ? g_qin_lo : (z == 1) ? g_kin_lo : g_vin_lo;
        split4f(src, hi, lo, i);
    } else if (z < 7) {
        if (i >= 512 * 512 / 4) return;
        int w = z - 3;
        const float* src = (w == 0) ? wq : (w == 1) ? wk : (w == 2) ? wv : wo;
        bf16* hi = (w == 0) ? g_Wq_hi : (w == 1) ? g_Wk_hi : (w == 2) ? g_Wv_hi : g_Wo_hi;
        bf16* lo = (w == 0) ? g_Wq_lo : (w == 1) ? g_Wk_lo : (w == 2) ? g_Wv_lo : g_Wo_lo;
        split4f(src, hi, lo, i);
    } else {
        if (i >= S_ * S_ / 4) return;
        float4 l4 = ((const float4*)ld)[i];
        int4 m4 = ((const int4*)mask)[i];
        float4 o;
        o.x = m4.x ? __expf(-l4.x) : -1.0f;
        o.y = m4.y ? __expf(-l4.y) : -1.0f;
        o.z = m4.z ? __expf(-l4.z) : -1.0f;
        o.w = m4.w ? __expf(-l4.w) : -1.0f;
        ((float4*)g_ctw)[i] = o;
    }
}

// ---------------------------------------------------------------------------
__device__ __forceinline__ void ldsm4(uint32_t addr, uint32_t& r0, uint32_t& r1,
                                      uint32_t& r2, uint32_t& r3) {
    asm volatile("ldmatrix.sync.aligned.m8n8.x4.shared.b16 {%0,%1,%2,%3}, [%4];"
                 : "=r"(r0), "=r"(r1), "=r"(r2), "=r"(r3) : "r"(addr));
}

__device__ __forceinline__ void mma16816(float* c, const uint32_t* a, const uint32_t* b) {
    asm volatile(
        "mma.sync.aligned.m16n8k16.row.col.f32.bf16.bf16.f32 "
        "{%0,%1,%2,%3}, {%4,%5,%6,%7}, {%8,%9}, {%0,%1,%2,%3};\n"
        : "+f"(c[0]), "+f"(c[1]), "+f"(c[2]), "+f"(c[3])
        : "r"(a[0]), "r"(a[1]), "r"(a[2]), "r"(a[3]), "r"(b[0]), "r"(b[1]));
}

__device__ __forceinline__ void cpa16(uint32_t dst, const void* src) {
    asm volatile("cp.async.cg.shared.global [%0], [%1], 16;" :: "r"(dst), "l"(src));
}
__device__ __forceinline__ void cp_commit() { asm volatile("cp.async.commit_group;"); }
template <int N>
__device__ __forceinline__ void cp_wait() { asm volatile("cp.async.wait_group %0;" :: "n"(N)); }

// [ROWS x 16] hi+lo tile loader, row layout [hi16|lo16|pad8], stride SK
template <int ROWS>
__device__ __forceinline__ void stage_load(const bf16* __restrict__ hi,
                                           const bf16* __restrict__ lo,
                                           int lda, int k0, uint32_t sdst, int tid) {
    #pragma unroll
    for (int i = 0; i < ROWS * 4 / 256; i++) {
        int idx = tid + i * 256;
        int r = idx >> 2, c = idx & 3;
        const bf16* src = ((c < 2) ? hi : lo) + (size_t)r * lda + k0 + (c & 1) * 8;
        uint32_t dst = sdst + (r * SK + ((c < 2) ? 0 : 16) + (c & 1) * 8) * 2;
        cpa16(dst, src);
    }
}

// ---------------------------------------------------------------------------
// 128x128 GEMM, 3xBF16, 4-stage cp.async pipeline, 1 sync/iter.
// Fragment reuse: aH/aL/bH/bL loaded once per k-step (12 LDSM, 48 MMA).
// MODE 5: fused QKV projections (z = 0/1/2 -> Q/K/V)
// MODE 2: scores (raw s + per-tile row stats)
// MODE 1: output projection -> fp32 out
// ---------------------------------------------------------------------------
template <int MODE>
__global__ __launch_bounds__(256, 2) void k_mm(
    const float* __restrict__ b0, const float* __restrict__ b1,
    const float* __restrict__ b2, float* __restrict__ out,
    const float* __restrict__ tbias) {
    constexpr int NST = 4;
    constexpr int STB = 256 * SK * 2;        // bytes per stage (A 128 rows + B 128 rows)
    constexpr int K = (MODE == 2) ? 64 : 512;
    constexpr int niter = K / BK;

    extern __shared__ char smraw[];
    float* red_s  = (float*)(smraw + NST * STB);        // [4][128]
    float* rowm_s = red_s + 4 * 128;

    const int tid = threadIdx.x, wid = tid >> 5, lane = tid & 31;
    const int wm = wid & 1, wn = wid >> 1;   // WARPS_M=2, WARPS_N=4; WM=64, WN=32
    const int bz = blockIdx.z;
    const int m0 = blockIdx.y * 128, n0 = blockIdx.x * 128;

    const bf16 *Ahi, *Alo, *Bhi, *Blo;
    const float* bias = b0;
    if (MODE == 5) {
        if (bz == 0)      { Ahi = g_qin_hi; Alo = g_qin_lo; Bhi = g_Wq_hi; Blo = g_Wq_lo; bias = b0; }
        else if (bz == 1) { Ahi = g_kin_hi; Alo = g_kin_lo; Bhi = g_Wk_hi; Blo = g_Wk_lo; bias = b1; }
        else              { Ahi = g_vin_hi; Alo = g_vin_lo; Bhi = g_Wv_hi; Blo = g_Wv_lo; bias = b2; }
    } else if (MODE == 1) {
        Ahi = g_C_hi; Alo = g_C_lo; Bhi = g_Wo_hi; Blo = g_Wo_lo;
    } else {  // MODE 2
        size_t o = (size_t)bz * S_ * DH_;
        Ahi = g_Q_hi + o; Alo = g_Q_lo + o; Bhi = g_K_hi + o; Blo = g_K_lo + o;
    }
    const bf16* Ahp = Ahi + (size_t)m0 * K;
    const bf16* Alp = Alo + (size_t)m0 * K;
    const bf16* Bhp = Bhi + (size_t)n0 * K;
    const bf16* Blp = Blo + (size_t)n0 * K;

    float acc[4][4][4];
    #pragma unroll
    for (int i = 0; i < 4; i++)
        #pragma unroll
        for (int j = 0; j < 4; j++)
            #pragma unroll
            for (int q = 0; q < 4; q++) acc[i][j][q] = 0.f;

    const uint32_t sbase = (uint32_t)__cvta_generic_to_shared(smraw);
    const int t8 = lane >> 3, r8 = lane & 7;
    const int frow = r8 + 8 * (t8 & 1);
    const int fcol = 8 * (t8 >> 1);

    // prologue: stages 0..NST-2
    #pragma unroll
    for (int s = 0; s < NST - 1; s++) {
        stage_load<128>(Ahp, Alp, K, s * BK, sbase + s * STB, tid);
        stage_load<128>(Bhp, Blp, K, s * BK, sbase + s * STB + 128 * SK * 2, tid);
        cp_commit();
    }

    for (int it = 0; it < niter; it++) {
        cp_wait<NST - 2>();
        __syncthreads();
        int pf = it + NST - 1;
        if (pf < niter) {
            uint32_t sd = sbase + (pf % NST) * STB;
            stage_load<128>(Ahp, Alp, K, pf * BK, sd, tid);
            stage_load<128>(Bhp, Blp, K, pf * BK, sd + 128 * SK * 2, tid);
        }
        cp_commit();

        const uint32_t sA = sbase + (it % NST) * STB;
        const uint32_t sB = sA + 128 * SK * 2;

        // load A-hi, B-hi, B-lo once
        uint32_t aH[4][4], bH[4][2], bL[4][2];
        #pragma unroll
        for (int mf = 0; mf < 4; mf++) {
            uint32_t addr = sA + ((wm * 64 + mf * 16 + frow) * SK + fcol) * 2;
            ldsm4(addr, aH[mf][0], aH[mf][1], aH[mf][2], aH[mf][3]);
        }
        #pragma unroll
        for (int nf2 = 0; nf2 < 2; nf2++) {
            uint32_t r0, r1, r2, r3;
            uint32_t addr = sB + ((wn * 32 + nf2 * 16 + frow) * SK + fcol) * 2;
            ldsm4(addr, r0, r1, r2, r3);
            bH[2 * nf2][0] = r0;      bH[2 * nf2][1] = r2;
            bH[2 * nf2 + 1][0] = r1;  bH[2 * nf2 + 1][1] = r3;
            addr = sB + ((wn * 32 + nf2 * 16 + frow) * SK + 16 + fcol) * 2;
            ldsm4(addr, r0, r1, r2, r3);
            bL[2 * nf2][0] = r0;      bL[2 * nf2][1] = r2;
            bL[2 * nf2 + 1][0] = r1;  bL[2 * nf2 + 1][1] = r3;
        }
        // pass 1: hi*hi
        #pragma unroll
        for (int mf = 0; mf < 4; mf++)
            #pragma unroll
            for (int nf = 0; nf < 4; nf++)
                mma16816(acc[mf][nf], aH[mf], bH[nf]);
        // pass 2: hi*lo
        #pragma unroll
        for (int mf = 0; mf < 4; mf++)
            #pragma unroll
            for (int nf = 0; nf < 4; nf++)
                mma16816(acc[mf][nf], aH[mf], bL[nf]);
        // load A-lo (aH now dead), pass 3: lo*hi
        uint32_t aL[4][4];
        #pragma unroll
        for (int mf = 0; mf < 4; mf++) {
            uint32_t addr = sA + ((wm * 64 + mf * 16 + frow) * SK + 16 + fcol) * 2;
            ldsm4(addr, aL[mf][0], aL[mf][1], aL[mf][2], aL[mf][3]);
        }
        #pragma unroll
        for (int mf = 0; mf < 4; mf++)
            #pragma unroll
            for (int nf = 0; nf < 4; nf++)
                mma16816(acc[mf][nf], aL[mf], bH[nf]);
    }

    const int lrow = lane >> 2, lcol = (lane & 3) * 2;
    #pragma unroll
    for (int mf = 0; mf < 4; mf++) {
        #pragma unroll
        for (int nf = 0; nf < 4; nf++) {
            #pragma unroll
            for (int hh = 0; hh < 2; hh++) {
                int m = m0 + wm * 64 + mf * 16 + lrow + hh * 8;
                int n = n0 + wn * 32 + nf * 8 + lcol;
                float v0 = acc[mf][nf][2 * hh];
                float v1 = acc[mf][nf][2 * hh + 1];
                if (MODE == 5) {
                    int b = m >> 11, s = m & 2047;
                    int h = n >> 6, d = n & 63;
                    float x0 = v0 + bias[n], x1 = v1 + bias[n + 1];
                    bf16 h0 = __float2bfloat16(x0), h1 = __float2bfloat16(x1);
                    bf16 l0 = __float2bfloat16(x0 - __bfloat162float(h0));
                    bf16 l1 = __float2bfloat16(x1 - __bfloat162float(h1));
                    if (bz < 2) {
                        bf16* oh = (bz == 0) ? g_Q_hi : g_K_hi;
                        bf16* ol = (bz == 0) ? g_Q_lo : g_K_lo;
                        size_t o = (((size_t)(b * H_ + h) * S_ + s) << 6) + d;
                        *(bf162*)&oh[o] = __halves2bfloat162(h0, h1);
                        *(bf162*)&ol[o] = __halves2bfloat162(l0, l1);
                    } else {
                        size_t base = (size_t)(b * H_ + h) * DH_;
                        g_Vt_hi[(base + d) * S_ + s] = h0;
                        g_Vt_hi[(base + d + 1) * S_ + s] = h1;
                        g_Vt_lo[(base + d) * S_ + s] = l0;
                        g_Vt_lo[(base + d + 1) * S_ + s] = l1;
                    }
                } else if (MODE == 1) {
                    *(float2*)&out[(size_t)m * 512 + n] =
                        make_float2(v0 + bias[n], v1 + bias[n + 1]);
                } else {  // MODE 2: ctw carries both tw and mask sentinel
                    int h = bz & 7;
                    float tb = tbias[h];
                    size_t mn = (size_t)m * S_ + n;
                    float2 tw = *(const float2*)&g_ctw[mn];
                    float s0 = v0 * SCALE_ + tb * tw.x;
                    float s1 = v1 * SCALE_ + tb * tw.y;
                    if (tw.x < 0.f) s0 = -1e9f;
                    if (tw.y < 0.f) s1 = -1e9f;
                    *(float2*)&out[(size_t)bz * S_ * S_ + mn] = make_float2(s0, s1);
                    acc[mf][nf][2 * hh] = s0;
                    acc[mf][nf][2 * hh + 1] = s1;
                }
            }
        }
    }

    if (MODE == 2) {
        #pragma unroll
        for (int mf = 0; mf < 4; mf++) {
            #pragma unroll
            for (int hh = 0; hh < 2; hh++) {
                float mx = -INFINITY;
                #pragma unroll
                for (int nf = 0; nf < 4; nf++)
                    mx = fmaxf(mx, fmaxf(acc[mf][nf][2 * hh], acc[mf][nf][2 * hh + 1]));
                mx = fmaxf(mx, __shfl_xor_sync(0xffffffffu, mx, 1));
                mx = fmaxf(mx, __shfl_xor_sync(0xffffffffu, mx, 2));
                if ((lane & 3) == 0)
                    red_s[wn * 128 + wm * 64 + mf * 16 + lrow + hh * 8] = mx;
            }
        }
        __syncthreads();
        if (tid < 128) {
            float mx = red_s[tid];
            #pragma unroll
            for (int w = 1; w < 4; w++) mx = fmaxf(mx, red_s[w * 128 + tid]);
            rowm_s[tid] = mx;
        }
        __syncthreads();
        #pragma unroll
        for (int mf = 0; mf < 4; mf++) {
            #pragma unroll
            for (int hh = 0; hh < 2; hh++) {
                int row = wm * 64 + mf * 16 + lrow + hh * 8;
                float rm = rowm_s[row];
                float sm = 0.f;
                #pragma unroll
                for (int nf = 0; nf < 4; nf++)
                    sm += __expf(acc[mf][nf][2 * hh] - rm) +
                          __expf(acc[mf][nf][2 * hh + 1] - rm);
                sm += __shfl_xor_sync(0xffffffffu, sm, 1);
                sm += __shfl_xor_sync(0xffffffffu, sm, 2);
                if ((lane & 3) == 0) red_s[wn * 128 + row] = sm;
            }
        }
        __syncthreads();
        if (tid < 128) {
            float l = red_s[tid];
            #pragma unroll
            for (int w = 1; w < 4; w++) l += red_s[w * 128 + tid];
            size_t o = ((size_t)bz * 16 + blockIdx.x) * S_ + m0 + tid;
            g_pm[o] = rowm_s[tid];
            g_pl[o] = l;
        }
    }
}

// ---------------------------------------------------------------------------
// ctx: raw s -> softmax finalize (stats combined inline) -> fp32 P -> P.V.
// BK=32 per iter (64 iters), 3-stage cp.async, fragment-reuse mainloop. (R12)
// ---------------------------------------------------------------------------
__global__ __launch_bounds__(256, 2) void ctx_kernel(float* __restrict__ P) {
    extern __shared__ char smraw[];
    float* sm_m  = (float*)(smraw + 101376);
    float* sm_li = (float*)(smraw + 101888);

    const int tid = threadIdx.x, wid = tid >> 5, lane = tid & 31;
    const int wm = wid & 3, wn = wid >> 2;
    const int bz = blockIdx.z;
    const int b = bz >> 3, h = bz & 7;
    const int m0 = blockIdx.y * 128;

    float* Pbh = P + (size_t)bz * S_ * S_;
    const bf16* Vh0 = g_Vt_hi + (size_t)bz * DH_ * S_;
    const bf16* Vl0 = g_Vt_lo + (size_t)bz * DH_ * S_;

    const uint32_t sbase = (uint32_t)__cvta_generic_to_shared(smraw);
    const uint32_t uP = sbase + 82944;
    const int t8 = lane >> 3, r8 = lane & 7;
    const int frow = r8 + 8 * (t8 & 1), fcol = 8 * (t8 >> 1);
    const int lrow = lane >> 2, lcol = (lane & 3) * 2;

    auto loadS = [&](int it, int slot) {
        uint32_t dstb = sbase + slot * 18432;
        #pragma unroll
        for (int i = 0; i < 4; i++) {
            int idx = tid + i * 256;
            int r = idx >> 3, c = (idx & 7) * 4;
            cpa16(dstb + (r * 36 + c) * 4, Pbh + (size_t)(m0 + r) * S_ + it * 32 + c);
        }
    };
    auto loadV = [&](int it, int slot) {
        uint32_t dstb = sbase + 55296 + slot * 9216;
        #pragma unroll
        for (int i = 0; i < 2; i++) {
            int idx = tid + i * 256;
            int r = idx >> 3, c = idx & 7;
            const bf16* src = ((c < 4) ? Vh0 : Vl0) + (size_t)r * S_ + it * 32 + (c & 3) * 8;
            cpa16(dstb + (r * 72 + ((c < 4) ? 0 : 32) + (c & 3) * 8) * 2, src);
        }
    };

    loadS(0, 0); loadV(0, 0); cp_commit();
    loadS(1, 1); loadV(1, 1); cp_commit();

    // inline stats combine — overlaps the prologue cp.async
    if (tid < 128) {
        int r = m0 + tid;
        float mt[16], mx = -INFINITY;
        #pragma unroll
        for (int t = 0; t < 16; t++) {
            mt[t] = g_pm[((size_t)bz * 16 + t) * S_ + r];
            mx = fmaxf(mx, mt[t]);
        }
        float l = 0.f;
        #pragma unroll
        for (int t = 0; t < 16; t++)
            l += g_pl[((size_t)bz * 16 + t) * S_ + r] * __expf(mt[t] - mx);
        sm_m[tid]  = mx;
        sm_li[tid] = 1.0f / l;
    }

    float acc[2][4][4];
    #pragma unroll
    for (int i = 0; i < 2; i++)
        #pragma unroll
        for (int j = 0; j < 4; j++)
            #pragma unroll
            for (int q = 0; q < 4; q++) acc[i][j][q] = 0.f;

    const int cr = tid >> 1, cb = (tid & 1) * 16;
    for (int it = 0; it < 64; it++) {
        cp_wait<1>();
        __syncthreads();

        // finalize p = exp(s - m) * linv, write fp32 P, split into sP
        {
            const float* ss = (const float*)(smraw + (it % 3) * 18432) + cr * 36 + cb;
            float mrow = sm_m[cr], li = sm_li[cr];
            float p[16];
            #pragma unroll
            for (int i = 0; i < 16; i += 4) {
                float4 a = *(const float4*)(ss + i);
                p[i]     = __expf(a.x - mrow) * li;
                p[i + 1] = __expf(a.y - mrow) * li;
                p[i + 2] = __expf(a.z - mrow) * li;
                p[i + 3] = __expf(a.w - mrow) * li;
            }
            float* gdst = Pbh + (size_t)(m0 + cr) * S_ + it * 32 + cb;
            #pragma unroll
            for (int i = 0; i < 16; i += 4)
                *(float4*)(gdst + i) = make_float4(p[i], p[i + 1], p[i + 2], p[i + 3]);
            bf16* sp = (bf16*)(smraw + 82944) + cr * 72;
            #pragma unroll
            for (int i = 0; i < 16; i += 8) {
                uint4 hv, lv;
                #pragma unroll
                for (int j = 0; j < 8; j += 2) {
                    bf16 a0 = __float2bfloat16(p[i + j]);
                    bf16 a1 = __float2bfloat16(p[i + j + 1]);
                    ((bf162*)&hv)[j >> 1] = __halves2bfloat162(a0, a1);
                    ((bf162*)&lv)[j >> 1] = __halves2bfloat162(
                        __float2bfloat16(p[i + j] - __bfloat162float(a0)),
                        __float2bfloat16(p[i + j + 1] - __bfloat162float(a1)));
                }
                *(uint4*)(sp + cb + i) = hv;
                *(uint4*)(sp + 32 + cb + i) = lv;
            }
        }
        __syncthreads();

        const uint32_t sVt = sbase + 55296 + (it % 3) * 9216;
        #pragma unroll
        for (int ks = 0; ks < 32; ks += 16) {
            uint32_t pH[2][4], pL[2][4], vH[4][2], vL[4][2];
            #pragma unroll
            for (int mf = 0; mf < 2; mf++) {
                uint32_t base = uP + ((wm * 32 + mf * 16 + frow) * 72 + ks + fcol) * 2;
                ldsm4(base, pH[mf][0], pH[mf][1], pH[mf][2], pH[mf][3]);
                ldsm4(base + 64, pL[mf][0], pL[mf][1], pL[mf][2], pL[mf][3]);
            }
            #pragma unroll
            for (int nf2 = 0; nf2 < 2; nf2++) {
                uint32_t r0, r1, r2, r3;
                uint32_t base = sVt + ((wn * 32 + nf2 * 16 + frow) * 72 + ks + fcol) * 2;
                ldsm4(base, r0, r1, r2, r3);
                vH[2 * nf2][0] = r0;      vH[2 * nf2][1] = r2;
                vH[2 * nf2 + 1][0] = r1;  vH[2 * nf2 + 1][1] = r3;
                ldsm4(base + 64, r0, r1, r2, r3);
                vL[2 * nf2][0] = r0;      vL[2 * nf2][1] = r2;
                vL[2 * nf2 + 1][0] = r1;  vL[2 * nf2 + 1][1] = r3;
            }
            #pragma unroll
            for (int mf = 0; mf < 2; mf++)
                #pragma unroll
                for (int nf = 0; nf < 4; nf++)
                    mma16816(acc[mf][nf], pH[mf], vH[nf]);
            #pragma unroll
            for (int mf = 0; mf < 2; mf++)
                #pragma unroll
                for (int nf = 0; nf < 4; nf++)
                    mma16816(acc[mf][nf], pH[mf], vL[nf]);
            #pragma unroll
            for (int mf = 0; mf < 2; mf++)
                #pragma unroll
                for (int nf = 0; nf < 4; nf++)
                    mma16816(acc[mf][nf], pL[mf], vH[nf]);
        }

        if (it + 2 < 64) { loadS(it + 2, (it + 2) % 3); loadV(it + 2, (it + 2) % 3); }
        cp_commit();
    }

    #pragma unroll
    for (int mf = 0; mf < 2; mf++) {
        #pragma unroll
        for (int nf = 0; nf < 4; nf++) {
            #pragma unroll
            for (int hh = 0; hh < 2; hh++) {
                int m = m0 + wm * 32 + mf * 16 + lrow + hh * 8;
                int d = wn * 32 + nf * 8 + lcol;
                size_t o = ((size_t)b * S_ + m) * E_ + h * DH_ + d;
                float v0 = acc[mf][nf][2 * hh], v1 = acc[mf][nf][2 * hh + 1];
                bf16 h0 = __float2bfloat16(v0), h1 = __float2bfloat16(v1);
                *(bf162*)&g_C_hi[o] = __halves2bfloat162(h0, h1);
                *(bf162*)&g_C_lo[o] = __halves2bfloat162(
                    __float2bfloat16(v0 - __bfloat162float(h0)),
                    __float2bfloat16(v1 - __bfloat162float(h1)));
            }
        }
    }
}

// ---------------------------------------------------------------------------
extern "C" void kernel_launch(void* const* d_in, const int* in_sizes, int n_in,
                              void* d_out, int out_size) {
    const float* query = (const float*)d_in[0];
    const float* key   = (const float*)d_in[1];
    const float* value = (const float*)d_in[2];
    const int*   tmask = (const int*)d_in[3];
    const float* ldist = (const float*)d_in[4];
    const float* bq = (const float*)d_in[6];
    const float* bk = (const float*)d_in[8];
    const float* bv = (const float*)d_in[10];
    const float* bo = (const float*)d_in[12];
    const float* tbias = (const float*)d_in[13];

    float* out_attn  = (float*)d_out;
    float* out_probs = (float*)d_out + (size_t)B_ * S_ * E_;

    static int configured = 0;
    if (!configured) {
        cudaFuncSetAttribute(k_mm<5>, cudaFuncAttributeMaxDynamicSharedMemorySize, 84480);
        cudaFuncSetAttribute(k_mm<2>, cudaFuncAttributeMaxDynamicSharedMemorySize, 84480);
        cudaFuncSetAttribute(k_mm<1>, cudaFuncAttributeMaxDynamicSharedMemorySize, 84480);
        cudaFuncSetAttribute(ctx_kernel, cudaFuncAttributeMaxDynamicSharedMemorySize, 102400);
        configured = 1;
    }

    // preprocessing: one z-batched launch (inputs / weights / ctw)
    dim3 gprep(4096, 1, 8);
    prep_kernel<<<gprep, 256>>>(query, key, value,
                                (const float*)d_in[5], (const float*)d_in[7],
                                (const float*)d_in[9], (const float*)d_in[11],
                                ldist, tmask);

    // fused QKV projections
    dim3 gqkv(4, 32, 3);
    k_mm<5><<<gqkv, 256, 84480>>>(bq, bk, bv, nullptr, nullptr);

    // scores (raw s + per-tile stats)
    dim3 gs(16, 16, 16);
    k_mm<2><<<gs, 256, 84480>>>(nullptr, nullptr, nullptr, out_probs, tbias);

    // ctx: inline stats combine + softmax finalize + P.V
    dim3 gc(1, 16, 16);
    ctx_kernel<<<gc, 256, 102400>>>(out_probs);

    // output projection
    dim3 gp(4, 32, 1);
    k_mm<1><<<gp, 256, 84480>>>(bo, nullptr, nullptr, out_attn, nullptr);
}

// round 15
// speedup vs baseline: 1.1364x; 1.0882x over previous
#include <cuda_runtime.h>
#include <cuda_fp16.h>
#include <math.h>
#include <stdint.h>

#define B_ 2
#define S_ 2048
#define E_ 512
#define H_ 8
#define DH_ 64
#define SCALE_ 0.125f  // 64^-0.5

#define BK 16          // fp32-equiv k per mainloop iter (k_mm)
#define SK 40          // k_mm smem row stride: 16 hi + 16 lo + 8 pad = 80B

typedef __half hf;
typedef __half2 hf2;

// ---- scratch (device globals; allocation is forbidden) ----
__device__ hf g_qin_hi[4096 * 512], g_qin_lo[4096 * 512];
__device__ hf g_kin_hi[4096 * 512], g_kin_lo[4096 * 512];
__device__ hf g_vin_hi[4096 * 512], g_vin_lo[4096 * 512];
__device__ hf g_Wq_hi[512 * 512], g_Wq_lo[512 * 512];
__device__ hf g_Wk_hi[512 * 512], g_Wk_lo[512 * 512];
__device__ hf g_Wv_hi[512 * 512], g_Wv_lo[512 * 512];
__device__ hf g_Wo_hi[512 * 512], g_Wo_lo[512 * 512];
__device__ hf g_Q_hi[16 * 2048 * 64], g_Q_lo[16 * 2048 * 64];    // [bh][s][d]
__device__ hf g_K_hi[16 * 2048 * 64], g_K_lo[16 * 2048 * 64];    // [bh][s][d]
__device__ hf g_Vt_hi[16 * 64 * 2048], g_Vt_lo[16 * 64 * 2048];  // [bh][d][s]
__device__ hf g_C_hi[4096 * 512], g_C_lo[4096 * 512];            // ctx [m][e]
__device__ float g_ctw[S_ * S_];         // mask ? exp(-ld) : -1.0 sentinel
__device__ float g_pm[16 * 16 * 2048];   // [bh][ntile][row]
__device__ float g_pl[16 * 16 * 2048];

// ---------------------------------------------------------------------------
__device__ __forceinline__ void split4f(const float* __restrict__ src,
                                        hf* __restrict__ hi,
                                        hf* __restrict__ lo, int i) {
    float4 v = ((const float4*)src)[i];
    hf h0 = __float2half(v.x), h1 = __float2half(v.y);
    hf h2 = __float2half(v.z), h3 = __float2half(v.w);
    ((hf2*)hi)[2 * i]     = __halves2half2(h0, h1);
    ((hf2*)hi)[2 * i + 1] = __halves2half2(h2, h3);
    ((hf2*)lo)[2 * i] = __halves2half2(
        __float2half(v.x - __half2float(h0)),
        __float2half(v.y - __half2float(h1)));
    ((hf2*)lo)[2 * i + 1] = __halves2half2(
        __float2half(v.z - __half2float(h2)),
        __float2half(v.w - __half2float(h3)));
}

// one z-batched preprocessing launch:
//   z 0..2 : input splits   z 3..6 : weight splits   z 7 : ctw
__global__ void prep_kernel(const float* __restrict__ q, const float* __restrict__ k,
                            const float* __restrict__ v, const float* __restrict__ wq,
                            const float* __restrict__ wk, const float* __restrict__ wv,
                            const float* __restrict__ wo, const float* __restrict__ ld,
                            const int* __restrict__ mask) {
    int z = blockIdx.z;
    int i = blockIdx.x * 256 + threadIdx.x;
    if (z < 3) {
        if (i >= 4096 * 512 / 4) return;
        const float* src = (z == 0) ? q : (z == 1) ? k : v;
        hf* hi = (z == 0) ? g_qin_hi : (z == 1) ? g_kin_hi : g_vin_hi;
        hf* lo = (z == 0) ? g_qin_lo : (z == 1) ? g_kin_lo : g_vin_lo;
        split4f(src, hi, lo, i);
    } else if (z < 7) {
        if (i >= 512 * 512 / 4) return;
        int w = z - 3;
        const float* src = (w == 0) ? wq : (w == 1) ? wk : (w == 2) ? wv : wo;
        hf* hi = (w == 0) ? g_Wq_hi : (w == 1) ? g_Wk_hi : (w == 2) ? g_Wv_hi : g_Wo_hi;
        hf* lo = (w == 0) ? g_Wq_lo : (w == 1) ? g_Wk_lo : (w == 2) ? g_Wv_lo : g_Wo_lo;
        split4f(src, hi, lo, i);
    } else {
        if (i >= S_ * S_ / 4) return;
        float4 l4 = ((const float4*)ld)[i];
        int4 m4 = ((const int4*)mask)[i];
        float4 o;
        o.x = m4.x ? __expf(-l4.x) : -1.0f;
        o.y = m4.y ? __expf(-l4.y) : -1.0f;
        o.z = m4.z ? __expf(-l4.z) : -1.0f;
        o.w = m4.w ? __expf(-l4.w) : -1.0f;
        ((float4*)g_ctw)[i] = o;
    }
}

// ---------------------------------------------------------------------------
__device__ __forceinline__ void ldsm4(uint32_t addr, uint32_t& r0, uint32_t& r1,
                                      uint32_t& r2, uint32_t& r3) {
    asm volatile("ldmatrix.sync.aligned.m8n8.x4.shared.b16 {%0,%1,%2,%3}, [%4];"
                 : "=r"(r0), "=r"(r1), "=r"(r2), "=r"(r3) : "r"(addr));
}

__device__ __forceinline__ void mma16816(float* c, const uint32_t* a, const uint32_t* b) {
    asm volatile(
        "mma.sync.aligned.m16n8k16.row.col.f32.f16.f16.f32 "
        "{%0,%1,%2,%3}, {%4,%5,%6,%7}, {%8,%9}, {%0,%1,%2,%3};\n"
        : "+f"(c[0]), "+f"(c[1]), "+f"(c[2]), "+f"(c[3])
        : "r"(a[0]), "r"(a[1]), "r"(a[2]), "r"(a[3]), "r"(b[0]), "r"(b[1]));
}

__device__ __forceinline__ void cpa16(uint32_t dst, const void* src) {
    asm volatile("cp.async.cg.shared.global [%0], [%1], 16;" :: "r"(dst), "l"(src));
}
__device__ __forceinline__ void cp_commit() { asm volatile("cp.async.commit_group;"); }
template <int N>
__device__ __forceinline__ void cp_wait() { asm volatile("cp.async.wait_group %0;" :: "n"(N)); }

// [ROWS x 16] hi+lo tile loader, row layout [hi16|lo16|pad8], stride SK
template <int ROWS>
__device__ __forceinline__ void stage_load(const hf* __restrict__ hi,
                                           const hf* __restrict__ lo,
                                           int lda, int k0, uint32_t sdst, int tid) {
    #pragma unroll
    for (int i = 0; i < ROWS * 4 / 256; i++) {
        int idx = tid + i * 256;
        int r = idx >> 2, c = idx & 3;
        const hf* src = ((c < 2) ? hi : lo) + (size_t)r * lda + k0 + (c & 1) * 8;
        uint32_t dst = sdst + (r * SK + ((c < 2) ? 0 : 16) + (c & 1) * 8) * 2;
        cpa16(dst, src);
    }
}

// ---------------------------------------------------------------------------
// 128x128 GEMM, fp16 splits, 4-stage cp.async pipeline, 1 sync/iter.
// MODE 5 (QKV proj): 3-pass (aH.bH + aH.bL + aL.bH), err ~2^-22
// MODE 2 (scores) / MODE 1 (outproj): 2-pass (aH.bH + aH.bL), err ~2^-12
// ---------------------------------------------------------------------------
template <int MODE>
__global__ __launch_bounds__(256, 2) void k_mm(
    const float* __restrict__ b0, const float* __restrict__ b1,
    const float* __restrict__ b2, float* __restrict__ out,
    const float* __restrict__ tbias) {
    constexpr int NST = 4;
    constexpr int STB = 256 * SK * 2;        // bytes per stage (A 128 rows + B 128 rows)
    constexpr int K = (MODE == 2) ? 64 : 512;
    constexpr int niter = K / BK;
    constexpr int NPASS = (MODE == 5) ? 3 : 2;

    extern __shared__ char smraw[];
    float* red_s  = (float*)(smraw + NST * STB);        // [4][128]
    float* rowm_s = red_s + 4 * 128;

    const int tid = threadIdx.x, wid = tid >> 5, lane = tid & 31;
    const int wm = wid & 1, wn = wid >> 1;   // WARPS_M=2, WARPS_N=4; WM=64, WN=32
    const int bz = blockIdx.z;
    const int m0 = blockIdx.y * 128, n0 = blockIdx.x * 128;

    const hf *Ahi, *Alo, *Bhi, *Blo;
    const float* bias = b0;
    if (MODE == 5) {
        if (bz == 0)      { Ahi = g_qin_hi; Alo = g_qin_lo; Bhi = g_Wq_hi; Blo = g_Wq_lo; bias = b0; }
        else if (bz == 1) { Ahi = g_kin_hi; Alo = g_kin_lo; Bhi = g_Wk_hi; Blo = g_Wk_lo; bias = b1; }
        else              { Ahi = g_vin_hi; Alo = g_vin_lo; Bhi = g_Wv_hi; Blo = g_Wv_lo; bias = b2; }
    } else if (MODE == 1) {
        Ahi = g_C_hi; Alo = g_C_lo; Bhi = g_Wo_hi; Blo = g_Wo_lo;
    } else {  // MODE 2
        size_t o = (size_t)bz * S_ * DH_;
        Ahi = g_Q_hi + o; Alo = g_Q_lo + o; Bhi = g_K_hi + o; Blo = g_K_lo + o;
    }
    const hf* Ahp = Ahi + (size_t)m0 * K;
    const hf* Alp = Alo + (size_t)m0 * K;
    const hf* Bhp = Bhi + (size_t)n0 * K;
    const hf* Blp = Blo + (size_t)n0 * K;

    float acc[4][4][4];
    #pragma unroll
    for (int i = 0; i < 4; i++)
        #pragma unroll
        for (int j = 0; j < 4; j++)
            #pragma unroll
            for (int q = 0; q < 4; q++) acc[i][j][q] = 0.f;

    const uint32_t sbase = (uint32_t)__cvta_generic_to_shared(smraw);
    const int t8 = lane >> 3, r8 = lane & 7;
    const int frow = r8 + 8 * (t8 & 1);
    const int fcol = 8 * (t8 >> 1);

    // prologue: stages 0..NST-2
    #pragma unroll
    for (int s = 0; s < NST - 1; s++) {
        stage_load<128>(Ahp, Alp, K, s * BK, sbase + s * STB, tid);
        stage_load<128>(Bhp, Blp, K, s * BK, sbase + s * STB + 128 * SK * 2, tid);
        cp_commit();
    }

    for (int it = 0; it < niter; it++) {
        cp_wait<NST - 2>();
        __syncthreads();
        int pf = it + NST - 1;
        if (pf < niter) {
            uint32_t sd = sbase + (pf % NST) * STB;
            stage_load<128>(Ahp, Alp, K, pf * BK, sd, tid);
            stage_load<128>(Bhp, Blp, K, pf * BK, sd + 128 * SK * 2, tid);
        }
        cp_commit();

        const uint32_t sA = sbase + (it % NST) * STB;
        const uint32_t sB = sA + 128 * SK * 2;

        // load A-hi, B-hi, B-lo once
        uint32_t aH[4][4], bH[4][2], bL[4][2];
        #pragma unroll
        for (int mf = 0; mf < 4; mf++) {
            uint32_t addr = sA + ((wm * 64 + mf * 16 + frow) * SK + fcol) * 2;
            ldsm4(addr, aH[mf][0], aH[mf][1], aH[mf][2], aH[mf][3]);
        }
        #pragma unroll
        for (int nf2 = 0; nf2 < 2; nf2++) {
            uint32_t r0, r1, r2, r3;
            uint32_t addr = sB + ((wn * 32 + nf2 * 16 + frow) * SK + fcol) * 2;
            ldsm4(addr, r0, r1, r2, r3);
            bH[2 * nf2][0] = r0;      bH[2 * nf2][1] = r2;
            bH[2 * nf2 + 1][0] = r1;  bH[2 * nf2 + 1][1] = r3;
            addr = sB + ((wn * 32 + nf2 * 16 + frow) * SK + 16 + fcol) * 2;
            ldsm4(addr, r0, r1, r2, r3);
            bL[2 * nf2][0] = r0;      bL[2 * nf2][1] = r2;
            bL[2 * nf2 + 1][0] = r1;  bL[2 * nf2 + 1][1] = r3;
        }
        // pass 1: hi*hi
        #pragma unroll
        for (int mf = 0; mf < 4; mf++)
            #pragma unroll
            for (int nf = 0; nf < 4; nf++)
                mma16816(acc[mf][nf], aH[mf], bH[nf]);
        // pass 2: hi*lo
        #pragma unroll
        for (int mf = 0; mf < 4; mf++)
            #pragma unroll
            for (int nf = 0; nf < 4; nf++)
                mma16816(acc[mf][nf], aH[mf], bL[nf]);
        // pass 3 (projections only): lo*hi
        if (NPASS == 3) {
            uint32_t aL[4][4];
            #pragma unroll
            for (int mf = 0; mf < 4; mf++) {
                uint32_t addr = sA + ((wm * 64 + mf * 16 + frow) * SK + 16 + fcol) * 2;
                ldsm4(addr, aL[mf][0], aL[mf][1], aL[mf][2], aL[mf][3]);
            }
            #pragma unroll
            for (int mf = 0; mf < 4; mf++)
                #pragma unroll
                for (int nf = 0; nf < 4; nf++)
                    mma16816(acc[mf][nf], aL[mf], bH[nf]);
        }
    }

    const int lrow = lane >> 2, lcol = (lane & 3) * 2;
    #pragma unroll
    for (int mf = 0; mf < 4; mf++) {
        #pragma unroll
        for (int nf = 0; nf < 4; nf++) {
            #pragma unroll
            for (int hh = 0; hh < 2; hh++) {
                int m = m0 + wm * 64 + mf * 16 + lrow + hh * 8;
                int n = n0 + wn * 32 + nf * 8 + lcol;
                float v0 = acc[mf][nf][2 * hh];
                float v1 = acc[mf][nf][2 * hh + 1];
                if (MODE == 5) {
                    int b = m >> 11, s = m & 2047;
                    int h = n >> 6, d = n & 63;
                    float x0 = v0 + bias[n], x1 = v1 + bias[n + 1];
                    hf h0 = __float2half(x0), h1 = __float2half(x1);
                    hf l0 = __float2half(x0 - __half2float(h0));
                    hf l1 = __float2half(x1 - __half2float(h1));
                    if (bz < 2) {
                        hf* oh = (bz == 0) ? g_Q_hi : g_K_hi;
                        hf* ol = (bz == 0) ? g_Q_lo : g_K_lo;
                        size_t o = (((size_t)(b * H_ + h) * S_ + s) << 6) + d;
                        *(hf2*)&oh[o] = __halves2half2(h0, h1);
                        *(hf2*)&ol[o] = __halves2half2(l0, l1);
                    } else {
                        size_t base = (size_t)(b * H_ + h) * DH_;
                        g_Vt_hi[(base + d) * S_ + s] = h0;
                        g_Vt_hi[(base + d + 1) * S_ + s] = h1;
                        g_Vt_lo[(base + d) * S_ + s] = l0;
                        g_Vt_lo[(base + d + 1) * S_ + s] = l1;
                    }
                } else if (MODE == 1) {
                    *(float2*)&out[(size_t)m * 512 + n] =
                        make_float2(v0 + bias[n], v1 + bias[n + 1]);
                } else {  // MODE 2: ctw carries both tw and mask sentinel
                    int h = bz & 7;
                    float tb = tbias[h];
                    size_t mn = (size_t)m * S_ + n;
                    float2 tw = *(const float2*)&g_ctw[mn];
                    float s0 = v0 * SCALE_ + tb * tw.x;
                    float s1 = v1 * SCALE_ + tb * tw.y;
                    if (tw.x < 0.f) s0 = -1e9f;
                    if (tw.y < 0.f) s1 = -1e9f;
                    *(float2*)&out[(size_t)bz * S_ * S_ + mn] = make_float2(s0, s1);
                    acc[mf][nf][2 * hh] = s0;
                    acc[mf][nf][2 * hh + 1] = s1;
                }
            }
        }
    }

    if (MODE == 2) {
        #pragma unroll
        for (int mf = 0; mf < 4; mf++) {
            #pragma unroll
            for (int hh = 0; hh < 2; hh++) {
                float mx = -INFINITY;
                #pragma unroll
                for (int nf = 0; nf < 4; nf++)
                    mx = fmaxf(mx, fmaxf(acc[mf][nf][2 * hh], acc[mf][nf][2 * hh + 1]));
                mx = fmaxf(mx, __shfl_xor_sync(0xffffffffu, mx, 1));
                mx = fmaxf(mx, __shfl_xor_sync(0xffffffffu, mx, 2));
                if ((lane & 3) == 0)
                    red_s[wn * 128 + wm * 64 + mf * 16 + lrow + hh * 8] = mx;
            }
        }
        __syncthreads();
        if (tid < 128) {
            float mx = red_s[tid];
            #pragma unroll
            for (int w = 1; w < 4; w++) mx = fmaxf(mx, red_s[w * 128 + tid]);
            rowm_s[tid] = mx;
        }
        __syncthreads();
        #pragma unroll
        for (int mf = 0; mf < 4; mf++) {
            #pragma unroll
            for (int hh = 0; hh < 2; hh++) {
                int row = wm * 64 + mf * 16 + lrow + hh * 8;
                float rm = rowm_s[row];
                float sm = 0.f;
                #pragma unroll
                for (int nf = 0; nf < 4; nf++)
                    sm += __expf(acc[mf][nf][2 * hh] - rm) +
                          __expf(acc[mf][nf][2 * hh + 1] - rm);
                sm += __shfl_xor_sync(0xffffffffu, sm, 1);
                sm += __shfl_xor_sync(0xffffffffu, sm, 2);
                if ((lane & 3) == 0) red_s[wn * 128 + row] = sm;
            }
        }
        __syncthreads();
        if (tid < 128) {
            float l = red_s[tid];
            #pragma unroll
            for (int w = 1; w < 4; w++) l += red_s[w * 128 + tid];
            size_t o = ((size_t)bz * 16 + blockIdx.x) * S_ + m0 + tid;
            g_pm[o] = rowm_s[tid];
            g_pl[o] = l;
        }
    }
}

// ---------------------------------------------------------------------------
// ctx: raw s -> softmax finalize (stats combined inline) -> fp32 P -> P.V.
// fp16 2-pass PV: pH.vH + pH.vL (sP hi-only). 3-stage cp.async, BK=32.
// ---------------------------------------------------------------------------
__global__ __launch_bounds__(256, 2) void ctx_kernel(float* __restrict__ P) {
    extern __shared__ char smraw[];
    float* sm_m  = (float*)(smraw + 101376);
    float* sm_li = (float*)(smraw + 101888);

    const int tid = threadIdx.x, wid = tid >> 5, lane = tid & 31;
    const int wm = wid & 3, wn = wid >> 2;
    const int bz = blockIdx.z;
    const int b = bz >> 3, h = bz & 7;
    const int m0 = blockIdx.y * 128;

    float* Pbh = P + (size_t)bz * S_ * S_;
    const hf* Vh0 = g_Vt_hi + (size_t)bz * DH_ * S_;
    const hf* Vl0 = g_Vt_lo + (size_t)bz * DH_ * S_;

    const uint32_t sbase = (uint32_t)__cvta_generic_to_shared(smraw);
    const uint32_t uP = sbase + 82944;
    const int t8 = lane >> 3, r8 = lane & 7;
    const int frow = r8 + 8 * (t8 & 1), fcol = 8 * (t8 >> 1);
    const int lrow = lane >> 2, lcol = (lane & 3) * 2;

    auto loadS = [&](int it, int slot) {
        uint32_t dstb = sbase + slot * 18432;
        #pragma unroll
        for (int i = 0; i < 4; i++) {
            int idx = tid + i * 256;
            int r = idx >> 3, c = (idx & 7) * 4;
            cpa16(dstb + (r * 36 + c) * 4, Pbh + (size_t)(m0 + r) * S_ + it * 32 + c);
        }
    };
    auto loadV = [&](int it, int slot) {
        uint32_t dstb = sbase + 55296 + slot * 9216;
        #pragma unroll
        for (int i = 0; i < 2; i++) {
            int idx = tid + i * 256;
            int r = idx >> 3, c = idx & 7;
            const hf* src = ((c < 4) ? Vh0 : Vl0) + (size_t)r * S_ + it * 32 + (c & 3) * 8;
            cpa16(dstb + (r * 72 + ((c < 4) ? 0 : 32) + (c & 3) * 8) * 2, src);
        }
    };

    loadS(0, 0); loadV(0, 0); cp_commit();
    loadS(1, 1); loadV(1, 1); cp_commit();

    // inline stats combine — overlaps the prologue cp.async
    if (tid < 128) {
        int r = m0 + tid;
        float mt[16], mx = -INFINITY;
        #pragma unroll
        for (int t = 0; t < 16; t++) {
            mt[t] = g_pm[((size_t)bz * 16 + t) * S_ + r];
            mx = fmaxf(mx, mt[t]);
        }
        float l = 0.f;
        #pragma unroll
        for (int t = 0; t < 16; t++)
            l += g_pl[((size_t)bz * 16 + t) * S_ + r] * __expf(mt[t] - mx);
        sm_m[tid]  = mx;
        sm_li[tid] = 1.0f / l;
    }

    float acc[2][4][4];
    #pragma unroll
    for (int i = 0; i < 2; i++)
        #pragma unroll
        for (int j = 0; j < 4; j++)
            #pragma unroll
            for (int q = 0; q < 4; q++) acc[i][j][q] = 0.f;

    const int cr = tid >> 1, cb = (tid & 1) * 16;
    for (int it = 0; it < 64; it++) {
        cp_wait<1>();
        __syncthreads();

        // finalize p = exp(s - m) * linv, write fp32 P, split hi into sP
        {
            const float* ss = (const float*)(smraw + (it % 3) * 18432) + cr * 36 + cb;
            float mrow = sm_m[cr], li = sm_li[cr];
            float p[16];
            #pragma unroll
            for (int i = 0; i < 16; i += 4) {
                float4 a = *(const float4*)(ss + i);
                p[i]     = __expf(a.x - mrow) * li;
                p[i + 1] = __expf(a.y - mrow) * li;
                p[i + 2] = __expf(a.z - mrow) * li;
                p[i + 3] = __expf(a.w - mrow) * li;
            }
            float* gdst = Pbh + (size_t)(m0 + cr) * S_ + it * 32 + cb;
            #pragma unroll
            for (int i = 0; i < 16; i += 4)
                *(float4*)(gdst + i) = make_float4(p[i], p[i + 1], p[i + 2], p[i + 3]);
            hf* sp = (hf*)(smraw + 82944) + cr * 72;
            #pragma unroll
            for (int i = 0; i < 16; i += 8) {
                uint4 hv;
                #pragma unroll
                for (int j = 0; j < 8; j += 2) {
                    ((hf2*)&hv)[j >> 1] = __halves2half2(
                        __float2half(p[i + j]), __float2half(p[i + j + 1]));
                }
                *(uint4*)(sp + cb + i) = hv;
            }
        }
        __syncthreads();

        const uint32_t sVt = sbase + 55296 + (it % 3) * 9216;
        #pragma unroll
        for (int ks = 0; ks < 32; ks += 16) {
            uint32_t pH[2][4], vH[4][2], vL[4][2];
            #pragma unroll
            for (int mf = 0; mf < 2; mf++) {
                uint32_t base = uP + ((wm * 32 + mf * 16 + frow) * 72 + ks + fcol) * 2;
                ldsm4(base, pH[mf][0], pH[mf][1], pH[mf][2], pH[mf][3]);
            }
            #pragma unroll
            for (int nf2 = 0; nf2 < 2; nf2++) {
                uint32_t r0, r1, r2, r3;
                uint32_t base = sVt + ((wn * 32 + nf2 * 16 + frow) * 72 + ks + fcol) * 2;
                ldsm4(base, r0, r1, r2, r3);
                vH[2 * nf2][0] = r0;      vH[2 * nf2][1] = r2;
                vH[2 * nf2 + 1][0] = r1;  vH[2 * nf2 + 1][1] = r3;
                ldsm4(base + 64, r0, r1, r2, r3);
                vL[2 * nf2][0] = r0;      vL[2 * nf2][1] = r2;
                vL[2 * nf2 + 1][0] = r1;  vL[2 * nf2 + 1][1] = r3;
            }
            #pragma unroll
            for (int mf = 0; mf < 2; mf++)
                #pragma unroll
                for (int nf = 0; nf < 4; nf++)
                    mma16816(acc[mf][nf], pH[mf], vH[nf]);
            #pragma unroll
            for (int mf = 0; mf < 2; mf++)
                #pragma unroll
                for (int nf = 0; nf < 4; nf++)
                    mma16816(acc[mf][nf], pH[mf], vL[nf]);
        }

        if (it + 2 < 64) { loadS(it + 2, (it + 2) % 3); loadV(it + 2, (it + 2) % 3); }
        cp_commit();
    }

    #pragma unroll
    for (int mf = 0; mf < 2; mf++) {
        #pragma unroll
        for (int nf = 0; nf < 4; nf++) {
            #pragma unroll
            for (int hh = 0; hh < 2; hh++) {
                int m = m0 + wm * 32 + mf * 16 + lrow + hh * 8;
                int d = wn * 32 + nf * 8 + lcol;
                size_t o = ((size_t)b * S_ + m) * E_ + h * DH_ + d;
                float v0 = acc[mf][nf][2 * hh], v1 = acc[mf][nf][2 * hh + 1];
                hf h0 = __float2half(v0), h1 = __float2half(v1);
                *(hf2*)&g_C_hi[o] = __halves2half2(h0, h1);
                *(hf2*)&g_C_lo[o] = __halves2half2(
                    __float2half(v0 - __half2float(h0)),
                    __float2half(v1 - __half2float(h1)));
            }
        }
    }
}

// ---------------------------------------------------------------------------
extern "C" void kernel_launch(void* const* d_in, const int* in_sizes, int n_in,
                              void* d_out, int out_size) {
    const float* query = (const float*)d_in[0];
    const float* key   = (const float*)d_in[1];
    const float* value = (const float*)d_in[2];
    const int*   tmask = (const int*)d_in[3];
    const float* ldist = (const float*)d_in[4];
    const float* bq = (const float*)d_in[6];
    const float* bk = (const float*)d_in[8];
    const float* bv = (const float*)d_in[10];
    const float* bo = (const float*)d_in[12];
    const float* tbias = (const float*)d_in[13];

    float* out_attn  = (float*)d_out;
    float* out_probs = (float*)d_out + (size_t)B_ * S_ * E_;

    static int configured = 0;
    if (!configured) {
        cudaFuncSetAttribute(k_mm<5>, cudaFuncAttributeMaxDynamicSharedMemorySize, 84480);
        cudaFuncSetAttribute(k_mm<2>, cudaFuncAttributeMaxDynamicSharedMemorySize, 84480);
        cudaFuncSetAttribute(k_mm<1>, cudaFuncAttributeMaxDynamicSharedMemorySize, 84480);
        cudaFuncSetAttribute(ctx_kernel, cudaFuncAttributeMaxDynamicSharedMemorySize, 102400);
        configured = 1;
    }

    // preprocessing: one z-batched launch (inputs / weights / ctw)
    dim3 gprep(4096, 1, 8);
    prep_kernel<<<gprep, 256>>>(query, key, value,
                                (const float*)d_in[5], (const float*)d_in[7],
                                (const float*)d_in[9], (const float*)d_in[11],
                                ldist, tmask);

    // fused QKV projections (3-pass fp16)
    dim3 gqkv(4, 32, 3);
    k_mm<5><<<gqkv, 256, 84480>>>(bq, bk, bv, nullptr, nullptr);

    // scores (2-pass fp16; raw s + per-tile stats)
    dim3 gs(16, 16, 16);
    k_mm<2><<<gs, 256, 84480>>>(nullptr, nullptr, nullptr, out_probs, tbias);

    // ctx: inline stats combine + softmax finalize + P.V (2-pass fp16)
    dim3 gc(1, 16, 16);
    ctx_kernel<<<gc, 256, 102400>>>(out_probs);

    // output projection (2-pass fp16)
    dim3 gp(4, 32, 1);
    k_mm<1><<<gp, 256, 84480>>>(bo, nullptr, nullptr, out_attn, nullptr);
}

// round 16
// speedup vs baseline: 1.3671x; 1.2030x over previous
#include <cuda_runtime.h>
#include <cuda_fp16.h>
#include <math.h>
#include <stdint.h>

#define B_ 2
#define S_ 2048
#define E_ 512
#define H_ 8
#define DH_ 64
#define SCALE_ 0.125f  // 64^-0.5

#define BK 16          // fp32-equiv k per mainloop iter (k_mm)
#define SK 40          // k_mm smem row stride: 16 hi + 16 lo + 8 pad = 80B

typedef __half hf;
typedef __half2 hf2;

// ---- scratch (device globals; allocation is forbidden) ----
__device__ hf g_qin_hi[4096 * 512], g_qin_lo[4096 * 512];
__device__ hf g_kin_hi[4096 * 512], g_kin_lo[4096 * 512];
__device__ hf g_vin_hi[4096 * 512], g_vin_lo[4096 * 512];
__device__ hf g_Wq_hi[512 * 512], g_Wq_lo[512 * 512];
__device__ hf g_Wk_hi[512 * 512], g_Wk_lo[512 * 512];
__device__ hf g_Wv_hi[512 * 512], g_Wv_lo[512 * 512];
__device__ hf g_Wo_hi[512 * 512], g_Wo_lo[512 * 512];
__device__ hf g_Q_hi[16 * 2048 * 64], g_Q_lo[16 * 2048 * 64];    // [bh][s][d]
__device__ hf g_K_hi[16 * 2048 * 64], g_K_lo[16 * 2048 * 64];    // [bh][s][d]
__device__ hf g_Vt_hi[16 * 64 * 2048], g_Vt_lo[16 * 64 * 2048];  // [bh][d][s]
__device__ hf g_C_hi[4096 * 512], g_C_lo[4096 * 512];            // ctx [m][e]
__device__ hf g_T[16ll * 2048 * 2048];   // tile-local probs t = exp(s - m_tile), fp16
__device__ float g_ctw[S_ * S_];         // mask ? exp(-ld) : -1.0 sentinel
__device__ float g_pm[16 * 16 * 2048];   // [bh][ntile][row] tile max
__device__ float g_pl[16 * 16 * 2048];   // [bh][ntile][row] tile sumexp

// ---------------------------------------------------------------------------
__device__ __forceinline__ void split4f(const float* __restrict__ src,
                                        hf* __restrict__ hi,
                                        hf* __restrict__ lo, int i) {
    float4 v = ((const float4*)src)[i];
    hf h0 = __float2half(v.x), h1 = __float2half(v.y);
    hf h2 = __float2half(v.z), h3 = __float2half(v.w);
    ((hf2*)hi)[2 * i]     = __halves2half2(h0, h1);
    ((hf2*)hi)[2 * i + 1] = __halves2half2(h2, h3);
    ((hf2*)lo)[2 * i] = __halves2half2(
        __float2half(v.x - __half2float(h0)),
        __float2half(v.y - __half2float(h1)));
    ((hf2*)lo)[2 * i + 1] = __halves2half2(
        __float2half(v.z - __half2float(h2)),
        __float2half(v.w - __half2float(h3)));
}

// one z-batched preprocessing launch:
//   z 0..2 : input splits   z 3..6 : weight splits   z 7 : ctw
__global__ void prep_kernel(const float* __restrict__ q, const float* __restrict__ k,
                            const float* __restrict__ v, const float* __restrict__ wq,
                            const float* __restrict__ wk, const float* __restrict__ wv,
                            const float* __restrict__ wo, const float* __restrict__ ld,
                            const int* __restrict__ mask) {
    int z = blockIdx.z;
    int i = blockIdx.x * 256 + threadIdx.x;
    if (z < 3) {
        if (i >= 4096 * 512 / 4) return;
        const float* src = (z == 0) ? q : (z == 1) ? k : v;
        hf* hi = (z == 0) ? g_qin_hi : (z == 1) ? g_kin_hi : g_vin_hi;
        hf* lo = (z == 0) ? g_qin_lo : (z == 1) ? g_kin_lo : g_vin_lo;
        split4f(src, hi, lo, i);
    } else if (z < 7) {
        if (i >= 512 * 512 / 4) return;
        int w = z - 3;
        const float* src = (w == 0) ? wq : (w == 1) ? wk : (w == 2) ? wv : wo;
        hf* hi = (w == 0) ? g_Wq_hi : (w == 1) ? g_Wk_hi : (w == 2) ? g_Wv_hi : g_Wo_hi;
        hf* lo = (w == 0) ? g_Wq_lo : (w == 1) ? g_Wk_lo : (w == 2) ? g_Wv_lo : g_Wo_lo;
        split4f(src, hi, lo, i);
    } else {
        if (i >= S_ * S_ / 4) return;
        float4 l4 = ((const float4*)ld)[i];
        int4 m4 = ((const int4*)mask)[i];
        float4 o;
        o.x = m4.x ? __expf(-l4.x) : -1.0f;
        o.y = m4.y ? __expf(-l4.y) : -1.0f;
        o.z = m4.z ? __expf(-l4.z) : -1.0f;
        o.w = m4.w ? __expf(-l4.w) : -1.0f;
        ((float4*)g_ctw)[i] = o;
    }
}

// ---------------------------------------------------------------------------
__device__ __forceinline__ void ldsm4(uint32_t addr, uint32_t& r0, uint32_t& r1,
                                      uint32_t& r2, uint32_t& r3) {
    asm volatile("ldmatrix.sync.aligned.m8n8.x4.shared.b16 {%0,%1,%2,%3}, [%4];"
                 : "=r"(r0), "=r"(r1), "=r"(r2), "=r"(r3) : "r"(addr));
}

__device__ __forceinline__ void mma16816(float* c, const uint32_t* a, const uint32_t* b) {
    asm volatile(
        "mma.sync.aligned.m16n8k16.row.col.f32.f16.f16.f32 "
        "{%0,%1,%2,%3}, {%4,%5,%6,%7}, {%8,%9}, {%0,%1,%2,%3};\n"
        : "+f"(c[0]), "+f"(c[1]), "+f"(c[2]), "+f"(c[3])
        : "r"(a[0]), "r"(a[1]), "r"(a[2]), "r"(a[3]), "r"(b[0]), "r"(b[1]));
}

__device__ __forceinline__ void cpa16(uint32_t dst, const void* src) {
    asm volatile("cp.async.cg.shared.global [%0], [%1], 16;" :: "r"(dst), "l"(src));
}
__device__ __forceinline__ void cp_commit() { asm volatile("cp.async.commit_group;"); }
template <int N>
__device__ __forceinline__ void cp_wait() { asm volatile("cp.async.wait_group %0;" :: "n"(N)); }

// [ROWS x 16] hi+lo tile loader, row layout [hi16|lo16|pad8], stride SK
template <int ROWS>
__device__ __forceinline__ void stage_load(const hf* __restrict__ hi,
                                           const hf* __restrict__ lo,
                                           int lda, int k0, uint32_t sdst, int tid) {
    #pragma unroll
    for (int i = 0; i < ROWS * 4 / 256; i++) {
        int idx = tid + i * 256;
        int r = idx >> 2, c = idx & 3;
        const hf* src = ((c < 2) ? hi : lo) + (size_t)r * lda + k0 + (c & 1) * 8;
        uint32_t dst = sdst + (r * SK + ((c < 2) ? 0 : 16) + (c & 1) * 8) * 2;
        cpa16(dst, src);
    }
}

// ---------------------------------------------------------------------------
// 128x128 GEMM, fp16 splits, 4-stage cp.async pipeline, 1 sync/iter.
// MODE 5 (QKV proj): 3-pass   MODE 2 (scores -> fp16 t + stats): 2-pass
// MODE 1 (outproj): 2-pass
// ---------------------------------------------------------------------------
template <int MODE>
__global__ __launch_bounds__(256, 2) void k_mm(
    const float* __restrict__ b0, const float* __restrict__ b1,
    const float* __restrict__ b2, float* __restrict__ out,
    const float* __restrict__ tbias) {
    constexpr int NST = 4;
    constexpr int STB = 256 * SK * 2;
    constexpr int K = (MODE == 2) ? 64 : 512;
    constexpr int niter = K / BK;
    constexpr int NPASS = (MODE == 5) ? 3 : 2;

    extern __shared__ char smraw[];
    float* red_s  = (float*)(smraw + NST * STB);        // [4][128]
    float* rowm_s = red_s + 4 * 128;

    const int tid = threadIdx.x, wid = tid >> 5, lane = tid & 31;
    const int wm = wid & 1, wn = wid >> 1;   // WARPS_M=2, WARPS_N=4; WM=64, WN=32
    const int bz = blockIdx.z;
    const int m0 = blockIdx.y * 128, n0 = blockIdx.x * 128;

    const hf *Ahi, *Alo, *Bhi, *Blo;
    const float* bias = b0;
    if (MODE == 5) {
        if (bz == 0)      { Ahi = g_qin_hi; Alo = g_qin_lo; Bhi = g_Wq_hi; Blo = g_Wq_lo; bias = b0; }
        else if (bz == 1) { Ahi = g_kin_hi; Alo = g_kin_lo; Bhi = g_Wk_hi; Blo = g_Wk_lo; bias = b1; }
        else              { Ahi = g_vin_hi; Alo = g_vin_lo; Bhi = g_Wv_hi; Blo = g_Wv_lo; bias = b2; }
    } else if (MODE == 1) {
        Ahi = g_C_hi; Alo = g_C_lo; Bhi = g_Wo_hi; Blo = g_Wo_lo;
    } else {  // MODE 2
        size_t o = (size_t)bz * S_ * DH_;
        Ahi = g_Q_hi + o; Alo = g_Q_lo + o; Bhi = g_K_hi + o; Blo = g_K_lo + o;
    }
    const hf* Ahp = Ahi + (size_t)m0 * K;
    const hf* Alp = Alo + (size_t)m0 * K;
    const hf* Bhp = Bhi + (size_t)n0 * K;
    const hf* Blp = Blo + (size_t)n0 * K;

    float acc[4][4][4];
    #pragma unroll
    for (int i = 0; i < 4; i++)
        #pragma unroll
        for (int j = 0; j < 4; j++)
            #pragma unroll
            for (int q = 0; q < 4; q++) acc[i][j][q] = 0.f;

    const uint32_t sbase = (uint32_t)__cvta_generic_to_shared(smraw);
    const int t8 = lane >> 3, r8 = lane & 7;
    const int frow = r8 + 8 * (t8 & 1);
    const int fcol = 8 * (t8 >> 1);

    #pragma unroll
    for (int s = 0; s < NST - 1; s++) {
        stage_load<128>(Ahp, Alp, K, s * BK, sbase + s * STB, tid);
        stage_load<128>(Bhp, Blp, K, s * BK, sbase + s * STB + 128 * SK * 2, tid);
        cp_commit();
    }

    for (int it = 0; it < niter; it++) {
        cp_wait<NST - 2>();
        __syncthreads();
        int pf = it + NST - 1;
        if (pf < niter) {
            uint32_t sd = sbase + (pf % NST) * STB;
            stage_load<128>(Ahp, Alp, K, pf * BK, sd, tid);
            stage_load<128>(Bhp, Blp, K, pf * BK, sd + 128 * SK * 2, tid);
        }
        cp_commit();

        const uint32_t sA = sbase + (it % NST) * STB;
        const uint32_t sB = sA + 128 * SK * 2;

        uint32_t aH[4][4], bH[4][2], bL[4][2];
        #pragma unroll
        for (int mf = 0; mf < 4; mf++) {
            uint32_t addr = sA + ((wm * 64 + mf * 16 + frow) * SK + fcol) * 2;
            ldsm4(addr, aH[mf][0], aH[mf][1], aH[mf][2], aH[mf][3]);
        }
        #pragma unroll
        for (int nf2 = 0; nf2 < 2; nf2++) {
            uint32_t r0, r1, r2, r3;
            uint32_t addr = sB + ((wn * 32 + nf2 * 16 + frow) * SK + fcol) * 2;
            ldsm4(addr, r0, r1, r2, r3);
            bH[2 * nf2][0] = r0;      bH[2 * nf2][1] = r2;
            bH[2 * nf2 + 1][0] = r1;  bH[2 * nf2 + 1][1] = r3;
            addr = sB + ((wn * 32 + nf2 * 16 + frow) * SK + 16 + fcol) * 2;
            ldsm4(addr, r0, r1, r2, r3);
            bL[2 * nf2][0] = r0;      bL[2 * nf2][1] = r2;
            bL[2 * nf2 + 1][0] = r1;  bL[2 * nf2 + 1][1] = r3;
        }
        #pragma unroll
        for (int mf = 0; mf < 4; mf++)
            #pragma unroll
            for (int nf = 0; nf < 4; nf++)
                mma16816(acc[mf][nf], aH[mf], bH[nf]);
        #pragma unroll
        for (int mf = 0; mf < 4; mf++)
            #pragma unroll
            for (int nf = 0; nf < 4; nf++)
                mma16816(acc[mf][nf], aH[mf], bL[nf]);
        if (NPASS == 3) {
            uint32_t aL[4][4];
            #pragma unroll
            for (int mf = 0; mf < 4; mf++) {
                uint32_t addr = sA + ((wm * 64 + mf * 16 + frow) * SK + 16 + fcol) * 2;
                ldsm4(addr, aL[mf][0], aL[mf][1], aL[mf][2], aL[mf][3]);
            }
            #pragma unroll
            for (int mf = 0; mf < 4; mf++)
                #pragma unroll
                for (int nf = 0; nf < 4; nf++)
                    mma16816(acc[mf][nf], aL[mf], bH[nf]);
        }
    }

    const int lrow = lane >> 2, lcol = (lane & 3) * 2;
    #pragma unroll
    for (int mf = 0; mf < 4; mf++) {
        #pragma unroll
        for (int nf = 0; nf < 4; nf++) {
            #pragma unroll
            for (int hh = 0; hh < 2; hh++) {
                int m = m0 + wm * 64 + mf * 16 + lrow + hh * 8;
                int n = n0 + wn * 32 + nf * 8 + lcol;
                float v0 = acc[mf][nf][2 * hh];
                float v1 = acc[mf][nf][2 * hh + 1];
                if (MODE == 5) {
                    int b = m >> 11, s = m & 2047;
                    int h = n >> 6, d = n & 63;
                    float x0 = v0 + bias[n], x1 = v1 + bias[n + 1];
                    hf h0 = __float2half(x0), h1 = __float2half(x1);
                    hf l0 = __float2half(x0 - __half2float(h0));
                    hf l1 = __float2half(x1 - __half2float(h1));
                    if (bz < 2) {
                        hf* oh = (bz == 0) ? g_Q_hi : g_K_hi;
                        hf* ol = (bz == 0) ? g_Q_lo : g_K_lo;
                        size_t o = (((size_t)(b * H_ + h) * S_ + s) << 6) + d;
                        *(hf2*)&oh[o] = __halves2half2(h0, h1);
                        *(hf2*)&ol[o] = __halves2half2(l0, l1);
                    } else {
                        size_t base = (size_t)(b * H_ + h) * DH_;
                        g_Vt_hi[(base + d) * S_ + s] = h0;
                        g_Vt_hi[(base + d + 1) * S_ + s] = h1;
                        g_Vt_lo[(base + d) * S_ + s] = l0;
                        g_Vt_lo[(base + d + 1) * S_ + s] = l1;
                    }
                } else if (MODE == 1) {
                    *(float2*)&out[(size_t)m * 512 + n] =
                        make_float2(v0 + bias[n], v1 + bias[n + 1]);
                } else {  // MODE 2: apply scale/bias/mask, keep s in registers
                    int h = bz & 7;
                    float tb = tbias[h];
                    size_t mn = (size_t)m * S_ + n;
                    float2 tw = *(const float2*)&g_ctw[mn];
                    float s0 = v0 * SCALE_ + tb * tw.x;
                    float s1 = v1 * SCALE_ + tb * tw.y;
                    if (tw.x < 0.f) s0 = -1e9f;
                    if (tw.y < 0.f) s1 = -1e9f;
                    acc[mf][nf][2 * hh] = s0;
                    acc[mf][nf][2 * hh + 1] = s1;
                }
            }
        }
    }

    if (MODE == 2) {
        // row-tile max
        #pragma unroll
        for (int mf = 0; mf < 4; mf++) {
            #pragma unroll
            for (int hh = 0; hh < 2; hh++) {
                float mx = -INFINITY;
                #pragma unroll
                for (int nf = 0; nf < 4; nf++)
                    mx = fmaxf(mx, fmaxf(acc[mf][nf][2 * hh], acc[mf][nf][2 * hh + 1]));
                mx = fmaxf(mx, __shfl_xor_sync(0xffffffffu, mx, 1));
                mx = fmaxf(mx, __shfl_xor_sync(0xffffffffu, mx, 2));
                if ((lane & 3) == 0)
                    red_s[wn * 128 + wm * 64 + mf * 16 + lrow + hh * 8] = mx;
            }
        }
        __syncthreads();
        if (tid < 128) {
            float mx = red_s[tid];
            #pragma unroll
            for (int w = 1; w < 4; w++) mx = fmaxf(mx, red_s[w * 128 + tid]);
            rowm_s[tid] = mx;
        }
        __syncthreads();
        // t = exp(s - m_tile): write fp16 t to g_T, accumulate tile sum
        hf* Tb = g_T + (size_t)bz * S_ * S_;
        #pragma unroll
        for (int mf = 0; mf < 4; mf++) {
            #pragma unroll
            for (int hh = 0; hh < 2; hh++) {
                int row = wm * 64 + mf * 16 + lrow + hh * 8;
                float rm = rowm_s[row];
                float sm = 0.f;
                #pragma unroll
                for (int nf = 0; nf < 4; nf++) {
                    float t0 = __expf(acc[mf][nf][2 * hh] - rm);
                    float t1 = __expf(acc[mf][nf][2 * hh + 1] - rm);
                    sm += t0 + t1;
                    int n = n0 + wn * 32 + nf * 8 + lcol;
                    *(hf2*)&Tb[(size_t)(m0 + row) * S_ + n] =
                        __halves2half2(__float2half(t0), __float2half(t1));
                }
                sm += __shfl_xor_sync(0xffffffffu, sm, 1);
                sm += __shfl_xor_sync(0xffffffffu, sm, 2);
                if ((lane & 3) == 0) red_s[wn * 128 + row] = sm;
            }
        }
        __syncthreads();
        if (tid < 128) {
            float l = red_s[tid];
            #pragma unroll
            for (int w = 1; w < 4; w++) l += red_s[w * 128 + tid];
            size_t o = ((size_t)bz * 16 + blockIdx.x) * S_ + m0 + tid;
            g_pm[o] = rowm_s[tid];
            g_pl[o] = l;
        }
    }
}

// ---------------------------------------------------------------------------
// ctx: fp16 t -> p = t*f (writes fp32 P) + P.V with A-fragments LDSM'd straight
// from the staged t tiles; per-column-tile scale f applied via temp accumulator.
// smem: sS 3x10240 @0 | sV 3x9216 @30720 | sm_f 128x16 f32 @58368  (66560 B)
// ---------------------------------------------------------------------------
__global__ __launch_bounds__(256, 2) void ctx_kernel(float* __restrict__ P) {
    extern __shared__ char smraw[];
    float* sm_f = (float*)(smraw + 58368);

    const int tid = threadIdx.x, wid = tid >> 5, lane = tid & 31;
    const int wm = wid & 3, wn = wid >> 2;
    const int bz = blockIdx.z;
    const int b = bz >> 3, h = bz & 7;
    const int m0 = blockIdx.y * 128;

    float* Pbh = P + (size_t)bz * S_ * S_;
    const hf* Tbh = g_T + (size_t)bz * S_ * S_;
    const hf* Vh0 = g_Vt_hi + (size_t)bz * DH_ * S_;
    const hf* Vl0 = g_Vt_lo + (size_t)bz * DH_ * S_;

    const uint32_t sbase = (uint32_t)__cvta_generic_to_shared(smraw);
    const int t8 = lane >> 3, r8 = lane & 7;
    const int frow = r8 + 8 * (t8 & 1), fcol = 8 * (t8 >> 1);
    const int lrow = lane >> 2, lcol = (lane & 3) * 2;

    auto loadS = [&](int it, int slot) {   // fp16 t tile: 128 rows x 32 hf, stride 40 hf
        uint32_t dstb = sbase + slot * 10240;
        #pragma unroll
        for (int i = 0; i < 2; i++) {
            int idx = tid + i * 256;
            int r = idx >> 2, c = (idx & 3) * 8;
            cpa16(dstb + (r * 40 + c) * 2, Tbh + (size_t)(m0 + r) * S_ + it * 32 + c);
        }
    };
    auto loadV = [&](int it, int slot) {
        uint32_t dstb = sbase + 30720 + slot * 9216;
        #pragma unroll
        for (int i = 0; i < 2; i++) {
            int idx = tid + i * 256;
            int r = idx >> 3, c = idx & 7;
            const hf* src = ((c < 4) ? Vh0 : Vl0) + (size_t)r * S_ + it * 32 + (c & 3) * 8;
            cpa16(dstb + (r * 72 + ((c < 4) ? 0 : 32) + (c & 3) * 8) * 2, src);
        }
    };

    loadS(0, 0); loadV(0, 0); cp_commit();
    loadS(1, 1); loadV(1, 1); cp_commit();

    // stats combine -> per (row, col-tile) factor f = exp(m_tile - m)*linv
    if (tid < 128) {
        int r = m0 + tid;
        float mt[16], mx = -INFINITY;
        #pragma unroll
        for (int t = 0; t < 16; t++) {
            mt[t] = g_pm[((size_t)bz * 16 + t) * S_ + r];
            mx = fmaxf(mx, mt[t]);
        }
        float l = 0.f;
        #pragma unroll
        for (int t = 0; t < 16; t++)
            l += g_pl[((size_t)bz * 16 + t) * S_ + r] * __expf(mt[t] - mx);
        float linv = 1.0f / l;
        #pragma unroll
        for (int t = 0; t < 16; t++)
            sm_f[tid * 16 + t] = __expf(mt[t] - mx) * linv;
    }

    float acc[2][4][4], accT[2][4][4];
    #pragma unroll
    for (int i = 0; i < 2; i++)
        #pragma unroll
        for (int j = 0; j < 4; j++)
            #pragma unroll
            for (int q = 0; q < 4; q++) { acc[i][j][q] = 0.f; accT[i][j][q] = 0.f; }

    const int cr = tid >> 1, cb = (tid & 1) * 16;
    for (int it = 0; it < 64; it++) {
        cp_wait<1>();
        __syncthreads();   // slot (it%3) loaded; sm_f visible (it==0)

        if (it + 2 < 64) { loadS(it + 2, (it + 2) % 3); loadV(it + 2, (it + 2) % 3); }
        cp_commit();

        // convert: p = t * f -> fp32 P (mandatory output)
        {
            const hf* ss = (const hf*)(smraw + (it % 3) * 10240) + cr * 40 + cb;
            float f = sm_f[cr * 16 + (it >> 2)];
            float* gdst = Pbh + (size_t)(m0 + cr) * S_ + it * 32 + cb;
            #pragma unroll
            for (int i = 0; i < 16; i += 8) {
                uint4 tv = *(const uint4*)(ss + i);
                float4 o0, o1;
                float2 a0 = __half22float2(((const hf2*)&tv)[0]);
                float2 a1 = __half22float2(((const hf2*)&tv)[1]);
                float2 a2 = __half22float2(((const hf2*)&tv)[2]);
                float2 a3 = __half22float2(((const hf2*)&tv)[3]);
                o0 = make_float4(a0.x * f, a0.y * f, a1.x * f, a1.y * f);
                o1 = make_float4(a2.x * f, a2.y * f, a3.x * f, a3.y * f);
                *(float4*)(gdst + i) = o0;
                *(float4*)(gdst + i + 4) = o1;
            }
        }

        // MMA: A = t straight from staged tile; 2-pass over V hi/lo
        const uint32_t sT  = sbase + (it % 3) * 10240;
        const uint32_t sVt = sbase + 30720 + (it % 3) * 9216;
        #pragma unroll
        for (int ks = 0; ks < 32; ks += 16) {
            uint32_t tA[2][4], vH[4][2], vL[4][2];
            #pragma unroll
            for (int mf = 0; mf < 2; mf++) {
                uint32_t base = sT + ((wm * 32 + mf * 16 + frow) * 40 + ks + fcol) * 2;
                ldsm4(base, tA[mf][0], tA[mf][1], tA[mf][2], tA[mf][3]);
            }
            #pragma unroll
            for (int nf2 = 0; nf2 < 2; nf2++) {
                uint32_t r0, r1, r2, r3;
                uint32_t base = sVt + ((wn * 32 + nf2 * 16 + frow) * 72 + ks + fcol) * 2;
                ldsm4(base, r0, r1, r2, r3);
                vH[2 * nf2][0] = r0;      vH[2 * nf2][1] = r2;
                vH[2 * nf2 + 1][0] = r1;  vH[2 * nf2 + 1][1] = r3;
                ldsm4(base + 64, r0, r1, r2, r3);
                vL[2 * nf2][0] = r0;      vL[2 * nf2][1] = r2;
                vL[2 * nf2 + 1][0] = r1;  vL[2 * nf2 + 1][1] = r3;
            }
            #pragma unroll
            for (int mf = 0; mf < 2; mf++)
                #pragma unroll
                for (int nf = 0; nf < 4; nf++)
                    mma16816(accT[mf][nf], tA[mf], vH[nf]);
            #pragma unroll
            for (int mf = 0; mf < 2; mf++)
                #pragma unroll
                for (int nf = 0; nf < 4; nf++)
                    mma16816(accT[mf][nf], tA[mf], vL[nf]);
        }

        // column-tile boundary: fold accT into acc with per-row scale f
        if ((it & 3) == 3) {
            int ct = it >> 2;
            #pragma unroll
            for (int mf = 0; mf < 2; mf++) {
                #pragma unroll
                for (int hh = 0; hh < 2; hh++) {
                    int row = wm * 32 + mf * 16 + lrow + hh * 8;
                    float f = sm_f[row * 16 + ct];
                    #pragma unroll
                    for (int nf = 0; nf < 4; nf++) {
                        acc[mf][nf][2 * hh]     += accT[mf][nf][2 * hh] * f;
                        acc[mf][nf][2 * hh + 1] += accT[mf][nf][2 * hh + 1] * f;
                        accT[mf][nf][2 * hh] = 0.f;
                        accT[mf][nf][2 * hh + 1] = 0.f;
                    }
                }
            }
        }
    }

    #pragma unroll
    for (int mf = 0; mf < 2; mf++) {
        #pragma unroll
        for (int nf = 0; nf < 4; nf++) {
            #pragma unroll
            for (int hh = 0; hh < 2; hh++) {
                int m = m0 + wm * 32 + mf * 16 + lrow + hh * 8;
                int d = wn * 32 + nf * 8 + lcol;
                size_t o = ((size_t)b * S_ + m) * E_ + h * DH_ + d;
                float v0 = acc[mf][nf][2 * hh], v1 = acc[mf][nf][2 * hh + 1];
                hf h0 = __float2half(v0), h1 = __float2half(v1);
                *(hf2*)&g_C_hi[o] = __halves2half2(h0, h1);
                *(hf2*)&g_C_lo[o] = __halves2half2(
                    __float2half(v0 - __half2float(h0)),
                    __float2half(v1 - __half2float(h1)));
            }
        }
    }
}

// ---------------------------------------------------------------------------
extern "C" void kernel_launch(void* const* d_in, const int* in_sizes, int n_in,
                              void* d_out, int out_size) {
    const float* query = (const float*)d_in[0];
    const float* key   = (const float*)d_in[1];
    const float* value = (const float*)d_in[2];
    const int*   tmask = (const int*)d_in[3];
    const float* ldist = (const float*)d_in[4];
    const float* bq = (const float*)d_in[6];
    const float* bk = (const float*)d_in[8];
    const float* bv = (const float*)d_in[10];
    const float* bo = (const float*)d_in[12];
    const float* tbias = (const float*)d_in[13];

    float* out_attn  = (float*)d_out;
    float* out_probs = (float*)d_out + (size_t)B_ * S_ * E_;

    static int configured = 0;
    if (!configured) {
        cudaFuncSetAttribute(k_mm<5>, cudaFuncAttributeMaxDynamicSharedMemorySize, 84480);
        cudaFuncSetAttribute(k_mm<2>, cudaFuncAttributeMaxDynamicSharedMemorySize, 84480);
        cudaFuncSetAttribute(k_mm<1>, cudaFuncAttributeMaxDynamicSharedMemorySize, 84480);
        cudaFuncSetAttribute(ctx_kernel, cudaFuncAttributeMaxDynamicSharedMemorySize, 66560);
        configured = 1;
    }

    // preprocessing: one z-batched launch (inputs / weights / ctw)
    dim3 gprep(4096, 1, 8);
    prep_kernel<<<gprep, 256>>>(query, key, value,
                                (const float*)d_in[5], (const float*)d_in[7],
                                (const float*)d_in[9], (const float*)d_in[11],
                                ldist, tmask);

    // fused QKV projections (3-pass fp16)
    dim3 gqkv(4, 32, 3);
    k_mm<5><<<gqkv, 256, 84480>>>(bq, bk, bv, nullptr, nullptr);

    // scores (2-pass fp16; fp16 t + per-tile stats)
    dim3 gs(16, 16, 16);
    k_mm<2><<<gs, 256, 84480>>>(nullptr, nullptr, nullptr, nullptr, tbias);

    // ctx: stats combine + p = t*f (fp32 P) + P.V
    dim3 gc(1, 16, 16);
    ctx_kernel<<<gc, 256, 66560>>>(out_probs);

    // output projection (2-pass fp16)
    dim3 gp(4, 32, 1);
    k_mm<1><<<gp, 256, 84480>>>(bo, nullptr, nullptr, out_attn, nullptr);
}